// round 14
// baseline (speedup 1.0000x reference)
#include <cuda_runtime.h>
#include <math.h>

#define B_   32
#define N_   4096
#define S_   512
#define FULLMASK 0xffffffffu

__device__ float g_centroid[B_ * S_ * 3];
__device__ float g_groups[B_ * S_ * 96];   // [bs][c][k]
__device__ int   g_prog[B_];               // fps progress per batch

// ---------------- helpers -------------------------------------------------
__device__ __forceinline__ unsigned long long pk2(float lo, float hi) {
    unsigned long long r;
    asm("mov.b64 %0, {%1, %2};" : "=l"(r) : "f"(lo), "f"(hi));
    return r;
}
__device__ __forceinline__ void upk2(unsigned long long v, float& lo, float& hi) {
    asm("mov.b64 {%0, %1}, %2;" : "=f"(lo), "=f"(hi) : "l"(v));
}
__device__ __forceinline__ unsigned long long fma2_(unsigned long long a,
                                                   unsigned long long b,
                                                   unsigned long long c) {
    unsigned long long d;
    asm("fma.rn.f32x2 %0, %1, %2, %3;" : "=l"(d) : "l"(a), "l"(b), "l"(c));
    return d;
}
__device__ __forceinline__ unsigned short bh16(float x) {
    unsigned short r;
    asm("cvt.rn.bf16.f32 %0, %1;" : "=h"(r) : "f"(x));
    return r;
}
__device__ __forceinline__ float bf2f(unsigned short h) {
    return __uint_as_float((unsigned)h << 16);
}
__device__ __forceinline__ void bsplit(float x, unsigned short& h, unsigned short& l) {
    h = bh16(x);
    l = bh16(x - bf2f(h));
}
__device__ __forceinline__ unsigned pk16(unsigned short a, unsigned short b) {
    return (unsigned)a | ((unsigned)b << 16);
}
__device__ __forceinline__ unsigned bsplitw(float x) {
    unsigned short h, l;
    bsplit(x, h, l);
    return pk16(h, l);
}
__device__ __forceinline__ unsigned ford(float x) {
    unsigned b = __float_as_uint(x);
    return b ^ (((int)b >> 31) | 0x80000000u);
}
__device__ __forceinline__ void mma16(float* c, const unsigned* a,
                                      unsigned b0, unsigned b1) {
    asm("mma.sync.aligned.m16n8k16.row.col.f32.bf16.bf16.f32 "
        "{%0,%1,%2,%3},{%4,%5,%6,%7},{%8,%9},{%0,%1,%2,%3};"
        : "+f"(c[0]), "+f"(c[1]), "+f"(c[2]), "+f"(c[3])
        : "r"(a[0]), "r"(a[1]), "r"(a[2]), "r"(a[3]), "r"(b0), "r"(b1));
}
__device__ __forceinline__ float gelu_exact(float v) {
    return 0.5f * v * (1.0f + erff(v * 0.70710678118654752440f));
}

// ============ fused FPS (blocks 0..31) + KNN (blocks 32..147) =============
__global__ __launch_bounds__(1024) void fps_knn_kernel(
    const float* __restrict__ x, float* __restrict__ out) {
    extern __shared__ float smf[];
    int tid = threadIdx.x;
    int lane = tid & 31, warp = tid >> 5;

    if (blockIdx.x < 32) {
        // -------------------- FPS: 512 active threads --------------------
        float* sx0 = smf;
        float* sx1 = smf + 4096;
        float* sx2 = smf + 8192;
        unsigned long long* pb = (unsigned long long*)(smf + 12288);
        int b = blockIdx.x;
        const float* xb = x + (size_t)b * N_ * 3;

        float px[8], py[8], pz[8], dist[8];
        if (tid < 512) {
#pragma unroll
            for (int i = 0; i < 8; ++i) {
                int n = tid + i * 512;
                float a0 = xb[n * 3 + 0], a1 = xb[n * 3 + 1], a2 = xb[n * 3 + 2];
                px[i] = a0; py[i] = a1; pz[i] = a2;
                sx0[n] = a0; sx1[n] = a1; sx2[n] = a2;
                dist[i] = 1e10f;
            }
        }
        __syncthreads();

        int last = 0;
        for (int s = 0; s < S_; ++s) {
            if (tid < 512) {
                float c0 = sx0[last], c1 = sx1[last], c2 = sx2[last];
                if (tid == 0) {
                    int bs = b * S_ + s;
                    out[(size_t)bs * 67 + 0] = c0;
                    out[(size_t)bs * 67 + 1] = c1;
                    out[(size_t)bs * 67 + 2] = c2;
                    g_centroid[bs * 3 + 0] = c0;
                    g_centroid[bs * 3 + 1] = c1;
                    g_centroid[bs * 3 + 2] = c2;
                    __threadfence();
                    *(volatile int*)&g_prog[b] = s + 1;   // release
                }
                float bv = -1.0f;
                unsigned bi = 0;
#pragma unroll
                for (int i = 0; i < 8; ++i) {
                    float dx = px[i] - c0, dy = py[i] - c1, dz = pz[i] - c2;
                    float d = (dx * dx + dy * dy) + dz * dz;
                    float nd = fminf(dist[i], d);
                    dist[i] = nd;
                    if (nd > bv) { bv = nd; bi = (unsigned)(tid + i * 512); }
                }
                unsigned vb = __float_as_uint(bv);
                unsigned wmax = __reduce_max_sync(FULLMASK, vb);
                unsigned cand = (vb == wmax) ? bi : 0xffffffffu;
                unsigned widx = __reduce_min_sync(FULLMASK, cand);
                int par = s & 1;
                if (lane == 0)
                    pb[par * 16 + warp] =
                        ((unsigned long long)wmax << 32) |
                        (unsigned long long)(0xffffffffu - widx);
            }
            __syncthreads();
            if (tid < 512) {
                int par = s & 1;
                unsigned long long k = pb[par * 16 + (lane & 15)];
                unsigned kv = (unsigned)(k >> 32);
                unsigned bmax = __reduce_max_sync(FULLMASK, kv);
                unsigned enc = (kv == bmax) ? (unsigned)k : 0u;
                unsigned benc = __reduce_max_sync(FULLMASK, enc);
                last = (int)(0xffffffffu - benc);
            }
        }
    } else {
        // -------------------- KNN v5: progress-gated ---------------------
        float* sx0 = smf;
        float* sx1 = smf + 4096;
        float* sx2 = smf + 8192;
        float* sxs = smf + 12288;

        int k = blockIdx.x - 32;
        int b, part, nparts;
        if (k < 80) { b = k >> 2; part = k & 3; nparts = 4; }
        else { int k2 = k - 80; b = 20 + k2 / 3; part = k2 % 3; nparts = 3; }

        const float* xb = x + (size_t)b * N_ * 3;
        for (int i = tid; i < N_; i += 1024) {
            float a0 = xb[i * 3 + 0], a1 = xb[i * 3 + 1], a2 = xb[i * 3 + 2];
            sx0[i] = a0; sx1[i] = a1; sx2[i] = a2;
            sxs[i] = (a0 * a0 + a1 * a1) + a2 * a2;
        }
        __syncthreads();

        int W = nparts * 32;
        int wg = part * 32 + warp;
        for (int s = wg; s < S_; s += W) {
            while (*(volatile int*)&g_prog[b] <= s) {}
            __threadfence();   // acquire
            int bs = b * S_ + s;
            float c0 = g_centroid[bs * 3 + 0];
            float c1 = g_centroid[bs * 3 + 1];
            float c2 = g_centroid[bs * 3 + 2];
            float cs = (c0 * c0 + c1 * c1) + c2 * c2;

            unsigned lb, li, mb, mi;
            {   // init: points 0..31
                int n = lane;
                float dot = (c0 * sx0[n] + c1 * sx1[n]) + c2 * sx2[n];
                float d2  = (cs + sxs[n]) - 2.0f * dot;
                lb = ford(d2);
                li = (unsigned)n;
                mb = __reduce_max_sync(FULLMASK, lb);
                mi = __reduce_max_sync(FULLMASK, (lb == mb) ? li : 0u);
            }
            {   // tile: points 32..63
                int n = 32 + lane;
                float dot = (c0 * sx0[n] + c1 * sx1[n]) + c2 * sx2[n];
                float d2  = (cs + sxs[n]) - 2.0f * dot;
                unsigned db = ford(d2);
                bool cand = (db < mb) || (db == mb && (unsigned)n < mi);
                unsigned m = __ballot_sync(FULLMASK, cand);
                while (m) {
                    int src = __ffs(m) - 1;
                    m &= m - 1;
                    unsigned cdb = __shfl_sync(FULLMASK, db, src);
                    unsigned cn  = (unsigned)(32 + src);
                    if (cdb < mb || (cdb == mb && cn < mi)) {
                        if (lb == mb && li == mi) { lb = cdb; li = cn; }
                        mb = __reduce_max_sync(FULLMASK, lb);
                        mi = __reduce_max_sync(FULLMASK, (lb == mb) ? li : 0u);
                    }
                }
            }
            for (int base = 64; base < N_; base += 64) {
                int n1 = base + lane, n2 = n1 + 32;
                float dot1 = (c0 * sx0[n1] + c1 * sx1[n1]) + c2 * sx2[n1];
                float d21  = (cs + sxs[n1]) - 2.0f * dot1;
                float dot2 = (c0 * sx0[n2] + c1 * sx1[n2]) + c2 * sx2[n2];
                float d22  = (cs + sxs[n2]) - 2.0f * dot2;
                unsigned db1 = ford(d21), db2 = ford(d22);
                bool c1f = (db1 < mb) || (db1 == mb && (unsigned)n1 < mi);
                bool c2f = (db2 < mb) || (db2 == mb && (unsigned)n2 < mi);
                unsigned m1 = __ballot_sync(FULLMASK, c1f);
                unsigned m2 = __ballot_sync(FULLMASK, c2f);
                while (m1) {
                    int src = __ffs(m1) - 1;
                    m1 &= m1 - 1;
                    unsigned cdb = __shfl_sync(FULLMASK, db1, src);
                    unsigned cn  = (unsigned)(base + src);
                    if (cdb < mb || (cdb == mb && cn < mi)) {
                        if (lb == mb && li == mi) { lb = cdb; li = cn; }
                        mb = __reduce_max_sync(FULLMASK, lb);
                        mi = __reduce_max_sync(FULLMASK, (lb == mb) ? li : 0u);
                    }
                }
                while (m2) {
                    int src = __ffs(m2) - 1;
                    m2 &= m2 - 1;
                    unsigned cdb = __shfl_sync(FULLMASK, db2, src);
                    unsigned cn  = (unsigned)(base + 32 + src);
                    if (cdb < mb || (cdb == mb && cn < mi)) {
                        if (lb == mb && li == mi) { lb = cdb; li = cn; }
                        mb = __reduce_max_sync(FULLMASK, lb);
                        mi = __reduce_max_sync(FULLMASK, (lb == mb) ? li : 0u);
                    }
                }
            }
            float* gp = g_groups + (size_t)bs * 96;
            int idx = (int)li;
            gp[lane]      = sx0[idx] - c0;
            gp[32 + lane] = sx1[idx] - c1;
            gp[64 + lane] = sx2[idx] - c2;
        }
    }
}

// ================= per-group compute: 2 groups / iteration ================
#define PBh_   0
#define PBl_   2304
#define WVh_   4608
#define WVl_   6912
#define WG1h_  9216
#define WG1l_  11520
#define WG2h_  13824
#define WG2l_  16128
#define WA_    18432
#define WQKB_  18624
#define BV_    18752
#define BG1_   18816
#define BG2_   18880
#define BA_    18944
#define BNM_   19008
#define BNR_   19072
#define BNG_   19136
#define BNB_   19200
#define CB_    19264
#define H32_   19272
#define Hh_    23624
#define Hl_    25928
#define Uh_    28232
#define Ul_    30536
#define Vh_    32840
#define Vl_    35144
#define ATTh_  37448
#define ATTl_  38728
#define Th_    40008
#define Tl_    42312
#define G1h_   44616
#define G1l_   46920
#define LG_    49224
#define RBs_   51336
#define CAs_   51400
#define MP_    51464
#define SMTOT  51720
#define SCRQ_  19272
#define SCRK_  23368
#define SCRP_  27464

__global__ __launch_bounds__(512) void group_kernel(
    const float* __restrict__ w_alpha, const float* __restrict__ b_alpha,
    const float* __restrict__ bn_gamma, const float* __restrict__ bn_beta,
    const float* __restrict__ bn_mean,  const float* __restrict__ bn_var,
    const float* __restrict__ w_q, const float* __restrict__ b_q,
    const float* __restrict__ w_k, const float* __restrict__ b_k,
    const float* __restrict__ w_v, const float* __restrict__ b_v,
    const float* __restrict__ w_g1, const float* __restrict__ b_g1,
    const float* __restrict__ w_g2, const float* __restrict__ b_g2,
    float* __restrict__ out) {
    extern __shared__ float sm[];
    unsigned* su = (unsigned*)sm;
    int tid = threadIdx.x;
    int warp = tid >> 5, lane = tid & 31;
    int qg = lane >> 2, t4 = lane & 3;

    for (int i = tid; i < 4096; i += 512) {
        sm[SCRQ_ + i] = w_q[i];
        sm[SCRK_ + i] = w_k[i];
    }
    for (int i = tid; i < 2048; i += 512) {
        int d = i >> 5, cp = i & 31;
        int i0 = d * 64 + 2 * cp;
        unsigned short h0, l0, h1, l1;
        bsplit(w_v[i0], h0, l0); bsplit(w_v[i0 + 1], h1, l1);
        su[WVh_ + cp * 72 + d] = pk16(h0, h1);
        su[WVl_ + cp * 72 + d] = pk16(l0, l1);
        bsplit(w_g1[i0], h0, l0); bsplit(w_g1[i0 + 1], h1, l1);
        su[WG1h_ + cp * 72 + d] = pk16(h0, h1);
        su[WG1l_ + cp * 72 + d] = pk16(l0, l1);
        bsplit(w_g2[i0], h0, l0); bsplit(w_g2[i0 + 1], h1, l1);
        su[WG2h_ + cp * 72 + d] = pk16(h0, h1);
        su[WG2l_ + cp * 72 + d] = pk16(l0, l1);
    }
    if (tid < 64) {
        sm[BV_ + tid] = b_v[tid];
        sm[BG1_ + tid] = b_g1[tid]; sm[BG2_ + tid] = b_g2[tid];
        sm[BA_ + tid] = b_alpha[tid];
        sm[BNM_ + tid] = bn_mean[tid];
        sm[BNR_ + tid] = rsqrtf(bn_var[tid] + 1e-5f);
        sm[BNG_ + tid] = bn_gamma[tid];
        sm[BNB_ + tid] = bn_beta[tid];
    }
    __syncthreads();

    for (int i = tid; i < 4096; i += 512) {
        int c = i & 63, cc = i >> 6;
        float s = 0.f;
#pragma unroll 8
        for (int d = 0; d < 64; ++d)
            s += sm[SCRQ_ + d * 64 + c] * sm[SCRK_ + d * 64 + cc];
        sm[SCRP_ + cc * 64 + c] = s;
    }
    if (tid < 192) {
        int d = tid / 3, c = tid % 3;
        float sc = sm[BNR_ + d] * sm[BNG_ + d];
        sm[WA_ + c * 64 + d] = w_alpha[tid] * sc;
    }
    if (tid >= 192 && tid < 256) {
        int d = tid - 192;
        float sc = sm[BNR_ + d] * sm[BNG_ + d];
        float sh = sm[BNB_ + d] - sm[BNM_ + d] * sc;
        sm[BA_ + d] = sm[BA_ + d] * sc + sh;
    }
    if (tid >= 256 && tid < 320) {
        int c = tid - 256;
        float aq = 0.f, ak = 0.f;
#pragma unroll 8
        for (int d = 0; d < 64; ++d) {
            aq += sm[SCRQ_ + d * 64 + c] * b_k[d];
            ak += sm[SCRK_ + d * 64 + c] * b_q[d];
        }
        sm[WQKB_ + 2 * c]     = ak;
        sm[WQKB_ + 2 * c + 1] = aq;
    }
    if (tid == 511) {
        float s = 0.f;
        for (int d = 0; d < 64; ++d) s += b_q[d] * b_k[d];
        sm[CB_] = s;
    }
    __syncthreads();

    for (int i = tid; i < 2048; i += 512) {
        int ccp = i >> 6, c = i & 63;
        unsigned short h0, l0, h1, l1;
        bsplit(sm[SCRP_ + (2 * ccp) * 64 + c], h0, l0);
        bsplit(sm[SCRP_ + (2 * ccp + 1) * 64 + c], h1, l1);
        su[PBh_ + ccp * 72 + c] = pk16(h0, h1);
        su[PBl_ + ccp * 72 + c] = pk16(l0, l1);
    }
    __syncthreads();

    int mt0 = warp >> 3, nt = warp & 7;
    int agrp = warp & 1, ad8 = (warp >> 1) * 8;

    for (int p = blockIdx.x; p < B_ * S_ / 2; p += gridDim.x) {
        // ---- A ----
        {
            const float* gp = g_groups + ((size_t)(2 * p + agrp)) * 96;
            float gc0 = __ldg(gp + lane);
            float gc1 = __ldg(gp + 32 + lane);
            float gc2 = __ldg(gp + 64 + lane);
            int row = agrp * 32 + lane;
            float hv[8];
#pragma unroll
            for (int r = 0; r < 8; ++r) {
                int d = ad8 + r;
                float v = sm[WA_ + d] * gc0 + sm[WA_ + 64 + d] * gc1 +
                          sm[WA_ + 128 + d] * gc2 + sm[BA_ + d];
                v = gelu_exact(v);
                hv[r] = v;
                sm[H32_ + d * 68 + row] = v;
            }
#pragma unroll
            for (int r = 0; r < 4; ++r) {
                unsigned short h0, l0, h1, l1;
                bsplit(hv[2 * r], h0, l0); bsplit(hv[2 * r + 1], h1, l1);
                int kp = (ad8 >> 1) + r;
                su[Hh_ + row * 36 + kp] = pk16(h0, h1);
                su[Hl_ + row * 36 + kp] = pk16(l0, l1);
            }
        }
        __syncthreads();

        // ---- B ----
        {
            int n0 = nt * 8 + qg;
            float uh[2][4] = {}, ue[2][4] = {}, vh[2][4] = {}, ve[2][4] = {};
#pragma unroll
            for (int kt = 0; kt < 4; ++kt) {
                int kp0 = kt * 8 + t4, kp1 = kp0 + 4;
                unsigned pbh0 = su[PBh_ + kp0 * 72 + n0];
                unsigned pbh1 = su[PBh_ + kp1 * 72 + n0];
                unsigned pbl0 = su[PBl_ + kp0 * 72 + n0];
                unsigned pbl1 = su[PBl_ + kp1 * 72 + n0];
                unsigned wvh0 = su[WVh_ + kp0 * 72 + n0];
                unsigned wvh1 = su[WVh_ + kp1 * 72 + n0];
                unsigned wvl0 = su[WVl_ + kp0 * 72 + n0];
                unsigned wvl1 = su[WVl_ + kp1 * 72 + n0];
#pragma unroll
                for (int t = 0; t < 2; ++t) {
                    int ra0 = mt0 * 16 + t * 32 + qg, ra1 = ra0 + 8;
                    unsigned ah[4], al[4];
                    ah[0] = su[Hh_ + ra0 * 36 + kp0];
                    ah[1] = su[Hh_ + ra1 * 36 + kp0];
                    ah[2] = su[Hh_ + ra0 * 36 + kp1];
                    ah[3] = su[Hh_ + ra1 * 36 + kp1];
                    al[0] = su[Hl_ + ra0 * 36 + kp0];
                    al[1] = su[Hl_ + ra1 * 36 + kp0];
                    al[2] = su[Hl_ + ra0 * 36 + kp1];
                    al[3] = su[Hl_ + ra1 * 36 + kp1];
                    mma16(uh[t], ah, pbh0, pbh1);
                    mma16(ue[t], ah, pbl0, pbl1);
                    mma16(ue[t], al, pbh0, pbh1);
                    mma16(vh[t], ah, wvh0, wvh1);
                    mma16(ve[t], ah, wvl0, wvl1);
                    mma16(ve[t], al, wvh0, wvh1);
                }
            }
            int cc0 = nt * 8 + 2 * t4, cc1 = cc0 + 1;
            float bv0 = sm[BV_ + cc0], bv1 = sm[BV_ + cc1];
            int kpU = nt * 4 + t4;
#pragma unroll
            for (int t = 0; t < 2; ++t) {
                int ra0 = mt0 * 16 + t * 32 + qg, ra1 = ra0 + 8;
                float u0 = uh[t][0] + ue[t][0], u1 = uh[t][1] + ue[t][1];
                float u2 = uh[t][2] + ue[t][2], u3 = uh[t][3] + ue[t][3];
                float v0 = vh[t][0] + ve[t][0] + bv0, v1 = vh[t][1] + ve[t][1] + bv1;
                float v2 = vh[t][2] + ve[t][2] + bv0, v3 = vh[t][3] + ve[t][3] + bv1;
                unsigned short h0, l0, h1, l1;
                bsplit(u0, h0, l0); bsplit(u1, h1, l1);
                su[Uh_ + kpU * 72 + ra0] = pk16(h0, h1);
                su[Ul_ + kpU * 72 + ra0] = pk16(l0, l1);
                bsplit(u2, h0, l0); bsplit(u3, h1, l1);
                su[Uh_ + kpU * 72 + ra1] = pk16(h0, h1);
                su[Ul_ + kpU * 72 + ra1] = pk16(l0, l1);
                unsigned s0 = bsplitw(v0), s1 = bsplitw(v1);
                unsigned s2 = bsplitw(v2), s3 = bsplitw(v3);
                unsigned p0 = __shfl_xor_sync(FULLMASK, s0, 4);
                unsigned p1 = __shfl_xor_sync(FULLMASK, s1, 4);
                unsigned p2 = __shfl_xor_sync(FULLMASK, s2, 4);
                unsigned p3 = __shfl_xor_sync(FULLMASK, s3, 4);
                if ((qg & 1) == 0) {
                    int kv0 = t * 16 + mt0 * 8 + (qg >> 1);
                    int kv1 = kv0 + 4;
                    su[Vh_ + kv0 * 72 + cc0] = __byte_perm(s0, p0, 0x5410);
                    su[Vl_ + kv0 * 72 + cc0] = __byte_perm(s0, p0, 0x7632);
                    su[Vh_ + kv0 * 72 + cc1] = __byte_perm(s1, p1, 0x5410);
                    su[Vl_ + kv0 * 72 + cc1] = __byte_perm(s1, p1, 0x7632);
                    su[Vh_ + kv1 * 72 + cc0] = __byte_perm(s2, p2, 0x5410);
                    su[Vl_ + kv1 * 72 + cc0] = __byte_perm(s2, p2, 0x7632);
                    su[Vh_ + kv1 * 72 + cc1] = __byte_perm(s3, p3, 0x5410);
                    su[Vl_ + kv1 * 72 + cc1] = __byte_perm(s3, p3, 0x7632);
                }
            }
        }
        if (warp < 2) {
            int grp = warp;
            unsigned long long rc = 0;
#pragma unroll 8
            for (int cc = 0; cc < 64; ++cc) {
                float hv = sm[H32_ + cc * 68 + grp * 32 + lane];
                rc = fma2_(*(const unsigned long long*)&sm[WQKB_ + 2 * cc],
                           pk2(hv, hv), rc);
            }
            float rB, cA;
            upk2(rc, rB, cA);
            sm[RBs_ + grp * 32 + lane] = rB;
            sm[CAs_ + grp * 32 + lane] = cA;
        }
        __syncthreads();

        // ---- C ----
        {
            int grp = warp >> 3, cmt = (warp >> 2) & 1, cnt = warp & 3;
            int ra0 = grp * 32 + cmt * 16 + qg, ra1 = ra0 + 8;
            int n0 = grp * 32 + cnt * 8 + qg;
            float ch[4] = {0, 0, 0, 0}, ce[4] = {0, 0, 0, 0};
#pragma unroll
            for (int kt = 0; kt < 4; ++kt) {
                int kp0 = kt * 8 + t4, kp1 = kp0 + 4;
                unsigned ah[4], al[4];
                ah[0] = su[Hh_ + ra0 * 36 + kp0];
                ah[1] = su[Hh_ + ra1 * 36 + kp0];
                ah[2] = su[Hh_ + ra0 * 36 + kp1];
                ah[3] = su[Hh_ + ra1 * 36 + kp1];
                al[0] = su[Hl_ + ra0 * 36 + kp0];
                al[1] = su[Hl_ + ra1 * 36 + kp0];
                al[2] = su[Hl_ + ra0 * 36 + kp1];
                al[3] = su[Hl_ + ra1 * 36 + kp1];
                unsigned bh0 = su[Uh_ + kp0 * 72 + n0];
                unsigned bh1 = su[Uh_ + kp1 * 72 + n0];
                unsigned bl0 = su[Ul_ + kp0 * 72 + n0];
                unsigned bl1 = su[Ul_ + kp1 * 72 + n0];
                mma16(ch, ah, bh0, bh1);
                mma16(ce, ah, bl0, bl1);
                mma16(ce, al, bh0, bh1);
            }
            int jc0 = cnt * 8 + 2 * t4;
            sm[LG_ + ra0 * 33 + jc0]     = ch[0] + ce[0];
            sm[LG_ + ra0 * 33 + jc0 + 1] = ch[1] + ce[1];
            sm[LG_ + ra1 * 33 + jc0]     = ch[2] + ce[2];
            sm[LG_ + ra1 * 33 + jc0 + 1] = ch[3] + ce[3];
        }
        __syncthreads();

        // ---- softmax ----
        {
            float cb = sm[CB_];
#pragma unroll
            for (int k = 0; k < 4; ++k) {
                int r = warp + 16 * k;
                int grp = r >> 5, i = r & 31;
                float a = (sm[LG_ + r * 33 + lane] + sm[CAs_ + grp * 32 + i] +
                           sm[RBs_ + grp * 32 + lane] + cb) * 0.125f;
                float m = a;
#pragma unroll
                for (int off = 16; off; off >>= 1)
                    m = fmaxf(m, __shfl_xor_sync(FULLMASK, m, off));
                float e = expf(a - m);
                float s = e;
#pragma unroll
                for (int off = 16; off; off >>= 1)
                    s += __shfl_xor_sync(FULLMASK, s, off);
                float pf = e / s;
                unsigned w0 = bsplitw(pf);
                unsigned q0 = __shfl_xor_sync(FULLMASK, w0, 1);
                if ((lane & 1) == 0) {
                    int jp = lane >> 1;
                    su[ATTh_ + r * 20 + jp] = __byte_perm(w0, q0, 0x5410);
                    su[ATTl_ + r * 20 + jp] = __byte_perm(w0, q0, 0x7632);
                }
            }
        }
        __syncthreads();

        // ---- D ----
        float rr[8];
        {
            int n0 = nt * 8 + qg;
            int dc0 = nt * 8 + 2 * t4, dc1 = dc0 + 1;
            int kpT = nt * 4 + t4;
#pragma unroll
            for (int grp = 0; grp < 2; ++grp) {
                int ra0 = grp * 32 + mt0 * 16 + qg, ra1 = ra0 + 8;
                float rh[4] = {0, 0, 0, 0}, re[4] = {0, 0, 0, 0};
#pragma unroll
                for (int kt = 0; kt < 2; ++kt) {
                    int kp0 = kt * 8 + t4, kp1 = kp0 + 4;
                    unsigned ah[4], al[4];
                    ah[0] = su[ATTh_ + ra0 * 20 + kp0];
                    ah[1] = su[ATTh_ + ra1 * 20 + kp0];
                    ah[2] = su[ATTh_ + ra0 * 20 + kp1];
                    ah[3] = su[ATTh_ + ra1 * 20 + kp1];
                    al[0] = su[ATTl_ + ra0 * 20 + kp0];
                    al[1] = su[ATTl_ + ra1 * 20 + kp0];
                    al[2] = su[ATTl_ + ra0 * 20 + kp1];
                    al[3] = su[ATTl_ + ra1 * 20 + kp1];
                    int kg0 = grp * 16 + kp0, kg1 = grp * 16 + kp1;
                    unsigned bh0 = su[Vh_ + kg0 * 72 + n0];
                    unsigned bh1 = su[Vh_ + kg1 * 72 + n0];
                    unsigned bl0 = su[Vl_ + kg0 * 72 + n0];
                    unsigned bl1 = su[Vl_ + kg1 * 72 + n0];
                    mma16(rh, ah, bh0, bh1);
                    mma16(re, ah, bl0, bl1);
                    mma16(re, al, bh0, bh1);
                }
                float r0 = rh[0] + re[0], r1 = rh[1] + re[1];
                float r2 = rh[2] + re[2], r3 = rh[3] + re[3];
                rr[grp * 4 + 0] = r0; rr[grp * 4 + 1] = r1;
                rr[grp * 4 + 2] = r2; rr[grp * 4 + 3] = r3;
                float t0 = r0 + sm[H32_ + dc0 * 68 + ra0];
                float t1 = r1 + sm[H32_ + dc1 * 68 + ra0];
                float t2 = r2 + sm[H32_ + dc0 * 68 + ra1];
                float t3 = r3 + sm[H32_ + dc1 * 68 + ra1];
                unsigned short h0, l0, h1, l1;
                bsplit(t0, h0, l0); bsplit(t1, h1, l1);
                su[Th_ + ra0 * 36 + kpT] = pk16(h0, h1);
                su[Tl_ + ra0 * 36 + kpT] = pk16(l0, l1);
                bsplit(t2, h0, l0); bsplit(t3, h1, l1);
                su[Th_ + ra1 * 36 + kpT] = pk16(h0, h1);
                su[Tl_ + ra1 * 36 + kpT] = pk16(l0, l1);
            }
        }
        __syncthreads();

        // ---- E ----
        {
            int n0 = nt * 8 + qg;
            int dc0 = nt * 8 + 2 * t4, dc1 = dc0 + 1;
            float b0 = sm[BG1_ + dc0], b1 = sm[BG1_ + dc1];
            int kpT = nt * 4 + t4;
            float gh[2][4] = {}, ge[2][4] = {};
#pragma unroll
            for (int kt = 0; kt < 4; ++kt) {
                int kp0 = kt * 8 + t4, kp1 = kp0 + 4;
                unsigned bh0 = su[WG1h_ + kp0 * 72 + n0];
                unsigned bh1 = su[WG1h_ + kp1 * 72 + n0];
                unsigned bl0 = su[WG1l_ + kp0 * 72 + n0];
                unsigned bl1 = su[WG1l_ + kp1 * 72 + n0];
#pragma unroll
                for (int t = 0; t < 2; ++t) {
                    int ra0 = t * 32 + mt0 * 16 + qg, ra1 = ra0 + 8;
                    unsigned ah[4], al[4];
                    ah[0] = su[Th_ + ra0 * 36 + kp0];
                    ah[1] = su[Th_ + ra1 * 36 + kp0];
                    ah[2] = su[Th_ + ra0 * 36 + kp1];
                    ah[3] = su[Th_ + ra1 * 36 + kp1];
                    al[0] = su[Tl_ + ra0 * 36 + kp0];
                    al[1] = su[Tl_ + ra1 * 36 + kp0];
                    al[2] = su[Tl_ + ra0 * 36 + kp1];
                    al[3] = su[Tl_ + ra1 * 36 + kp1];
                    mma16(gh[t], ah, bh0, bh1);
                    mma16(ge[t], ah, bl0, bl1);
                    mma16(ge[t], al, bh0, bh1);
                }
            }
#pragma unroll
            for (int t = 0; t < 2; ++t) {
                int ra0 = t * 32 + mt0 * 16 + qg, ra1 = ra0 + 8;
                float g0 = gelu_exact(gh[t][0] + ge[t][0] + b0);
                float g1 = gelu_exact(gh[t][1] + ge[t][1] + b1);
                float g2 = gelu_exact(gh[t][2] + ge[t][2] + b0);
                float g3 = gelu_exact(gh[t][3] + ge[t][3] + b1);
                unsigned short h0, l0, h1, l1;
                bsplit(g0, h0, l0); bsplit(g1, h1, l1);
                su[G1h_ + ra0 * 36 + kpT] = pk16(h0, h1);
                su[G1l_ + ra0 * 36 + kpT] = pk16(l0, l1);
                bsplit(g2, h0, l0); bsplit(g3, h1, l1);
                su[G1h_ + ra1 * 36 + kpT] = pk16(h0, h1);
                su[G1l_ + ra1 * 36 + kpT] = pk16(l0, l1);
            }
        }
        __syncthreads();

        // ---- F ----
        {
            int n0 = nt * 8 + qg;
            int dc0 = nt * 8 + 2 * t4, dc1 = dc0 + 1;
            float b0 = sm[BG2_ + dc0], b1 = sm[BG2_ + dc1];
            float fh[2][4] = {}, fe[2][4] = {};
#pragma unroll
            for (int kt = 0; kt < 4; ++kt) {
                int kp0 = kt * 8 + t4, kp1 = kp0 + 4;
                unsigned bh0 = su[WG2h_ + kp0 * 72 + n0];
                unsigned bh1 = su[WG2h_ + kp1 * 72 + n0];
                unsigned bl0 = su[WG2l_ + kp0 * 72 + n0];
                unsigned bl1 = su[WG2l_ + kp1 * 72 + n0];
#pragma unroll
                for (int t = 0; t < 2; ++t) {
                    int ra0 = t * 32 + mt0 * 16 + qg, ra1 = ra0 + 8;
                    unsigned ah[4], al[4];
                    ah[0] = su[G1h_ + ra0 * 36 + kp0];
                    ah[1] = su[G1h_ + ra1 * 36 + kp0];
                    ah[2] = su[G1h_ + ra0 * 36 + kp1];
                    ah[3] = su[G1h_ + ra1 * 36 + kp1];
                    al[0] = su[G1l_ + ra0 * 36 + kp0];
                    al[1] = su[G1l_ + ra1 * 36 + kp0];
                    al[2] = su[G1l_ + ra0 * 36 + kp1];
                    al[3] = su[G1l_ + ra1 * 36 + kp1];
                    mma16(fh[t], ah, bh0, bh1);
                    mma16(fe[t], ah, bl0, bl1);
                    mma16(fe[t], al, bh0, bh1);
                }
            }
#pragma unroll
            for (int t = 0; t < 2; ++t) {
                float v0 = fh[t][0] + fe[t][0] + b0 + rr[t * 4 + 0];
                float v1 = fh[t][1] + fe[t][1] + b1 + rr[t * 4 + 1];
                float v2 = fh[t][2] + fe[t][2] + b0 + rr[t * 4 + 2];
                float v3 = fh[t][3] + fe[t][3] + b1 + rr[t * 4 + 3];
                float m0 = fmaxf(v0, v2), m1 = fmaxf(v1, v3);
#pragma unroll
                for (int off = 4; off < 32; off <<= 1) {
                    m0 = fmaxf(m0, __shfl_xor_sync(FULLMASK, m0, off));
                    m1 = fmaxf(m1, __shfl_xor_sync(FULLMASK, m1, off));
                }
                if (lane < 4) {
                    sm[MP_ + t * 128 + mt0 * 64 + nt * 8 + 2 * t4]     = m0;
                    sm[MP_ + t * 128 + mt0 * 64 + nt * 8 + 2 * t4 + 1] = m1;
                }
            }
        }
        __syncthreads();
        if (tid < 128) {
            int grp = tid >> 6, d = tid & 63;
            out[(size_t)(2 * p + grp) * 67 + 3 + d] =
                fmaxf(sm[MP_ + grp * 128 + d], sm[MP_ + grp * 128 + 64 + d]);
        }
        __syncthreads();
    }
}

// ============================ launch ======================================
extern "C" void kernel_launch(void* const* d_in, const int* in_sizes, int n_in,
                              void* d_out, int out_size) {
    (void)in_sizes; (void)n_in; (void)out_size;
    const float* x        = (const float*)d_in[0];
    const float* w_alpha  = (const float*)d_in[1];
    const float* b_alpha  = (const float*)d_in[2];
    const float* bn_gamma = (const float*)d_in[3];
    const float* bn_beta  = (const float*)d_in[4];
    const float* bn_mean  = (const float*)d_in[5];
    const float* bn_var   = (const float*)d_in[6];
    const float* w_q      = (const float*)d_in[7];
    const float* b_q      = (const float*)d_in[8];
    const float* w_k      = (const float*)d_in[9];
    const float* b_k      = (const float*)d_in[10];
    const float* w_v      = (const float*)d_in[11];
    const float* b_v      = (const float*)d_in[12];
    const float* w_g1     = (const float*)d_in[13];
    const float* b_g1     = (const float*)d_in[14];
    const float* w_g2     = (const float*)d_in[15];
    const float* b_g2     = (const float*)d_in[16];
    float* out = (float*)d_out;

    cudaFuncSetAttribute(fps_knn_kernel,
                         cudaFuncAttributeMaxDynamicSharedMemorySize, 65536);
    cudaFuncSetAttribute(group_kernel,
                         cudaFuncAttributeMaxDynamicSharedMemorySize, SMTOT * 4);

    fps_knn_kernel<<<148, 1024, 65536>>>(x, out);
    group_kernel<<<148, 512, SMTOT * 4>>>(w_alpha, b_alpha, bn_gamma, bn_beta,
                                          bn_mean, bn_var, w_q, b_q, w_k, b_k,
                                          w_v, b_v, w_g1, b_g1, w_g2, b_g2, out);
}

// round 15
// speedup vs baseline: 3.4475x; 3.4475x over previous
#include <cuda_runtime.h>
#include <math.h>

#define B_   32
#define N_   4096
#define S_   512
#define FULLMASK 0xffffffffu

__device__ float g_centroid[B_ * S_ * 3];
__device__ float g_groups[B_ * S_ * 96];   // [bs][c][k]

// ---------------- helpers -------------------------------------------------
__device__ __forceinline__ unsigned long long pk2(float lo, float hi) {
    unsigned long long r;
    asm("mov.b64 %0, {%1, %2};" : "=l"(r) : "f"(lo), "f"(hi));
    return r;
}
__device__ __forceinline__ void upk2(unsigned long long v, float& lo, float& hi) {
    asm("mov.b64 {%0, %1}, %2;" : "=f"(lo), "=f"(hi) : "l"(v));
}
__device__ __forceinline__ unsigned long long fma2_(unsigned long long a,
                                                   unsigned long long b,
                                                   unsigned long long c) {
    unsigned long long d;
    asm("fma.rn.f32x2 %0, %1, %2, %3;" : "=l"(d) : "l"(a), "l"(b), "l"(c));
    return d;
}
__device__ __forceinline__ unsigned short bh16(float x) {
    unsigned short r;
    asm("cvt.rn.bf16.f32 %0, %1;" : "=h"(r) : "f"(x));
    return r;
}
__device__ __forceinline__ float bf2f(unsigned short h) {
    return __uint_as_float((unsigned)h << 16);
}
__device__ __forceinline__ void bsplit(float x, unsigned short& h, unsigned short& l) {
    h = bh16(x);
    l = bh16(x - bf2f(h));
}
__device__ __forceinline__ unsigned pk16(unsigned short a, unsigned short b) {
    return (unsigned)a | ((unsigned)b << 16);
}
__device__ __forceinline__ unsigned bsplitw(float x) {
    unsigned short h, l;
    bsplit(x, h, l);
    return pk16(h, l);
}
__device__ __forceinline__ unsigned ford(float x) {
    unsigned b = __float_as_uint(x);
    return b ^ (((int)b >> 31) | 0x80000000u);
}
__device__ __forceinline__ void mma16(float* c, const unsigned* a,
                                      unsigned b0, unsigned b1) {
    asm("mma.sync.aligned.m16n8k16.row.col.f32.bf16.bf16.f32 "
        "{%0,%1,%2,%3},{%4,%5,%6,%7},{%8,%9},{%0,%1,%2,%3};"
        : "+f"(c[0]), "+f"(c[1]), "+f"(c[2]), "+f"(c[3])
        : "r"(a[0]), "r"(a[1]), "r"(a[2]), "r"(a[3]), "r"(b0), "r"(b1));
}
__device__ __forceinline__ float gelu_exact(float v) {
    return 0.5f * v * (1.0f + erff(v * 0.70710678118654752440f));
}

// ============================ FPS (512 thr, 8 pts/thr) ====================
__global__ __launch_bounds__(512) void fps_kernel(const float* __restrict__ x,
                                                  float* __restrict__ out) {
    extern __shared__ float smf[];
    float* sx0 = smf;
    float* sx1 = smf + 4096;
    float* sx2 = smf + 8192;
    unsigned long long* pb = (unsigned long long*)(smf + 12288);

    int b = blockIdx.x, tid = threadIdx.x;
    int lane = tid & 31, warp = tid >> 5;
    const float* xb = x + (size_t)b * N_ * 3;

    float px[8], py[8], pz[8], dist[8];
#pragma unroll
    for (int i = 0; i < 8; ++i) {
        int n = tid + i * 512;
        float a0 = xb[n * 3 + 0], a1 = xb[n * 3 + 1], a2 = xb[n * 3 + 2];
        px[i] = a0; py[i] = a1; pz[i] = a2;
        sx0[n] = a0; sx1[n] = a1; sx2[n] = a2;
        dist[i] = 1e10f;
    }
    __syncthreads();

    int last = 0;
    for (int s = 0; s < S_; ++s) {
        float c0 = sx0[last], c1 = sx1[last], c2 = sx2[last];
        if (tid == 0) {
            int bs = b * S_ + s;
            out[(size_t)bs * 67 + 0] = c0;
            out[(size_t)bs * 67 + 1] = c1;
            out[(size_t)bs * 67 + 2] = c2;
            g_centroid[bs * 3 + 0] = c0;
            g_centroid[bs * 3 + 1] = c1;
            g_centroid[bs * 3 + 2] = c2;
        }
        float bv = -1.0f;
        unsigned bi = 0;
#pragma unroll
        for (int i = 0; i < 8; ++i) {
            float dx = px[i] - c0, dy = py[i] - c1, dz = pz[i] - c2;
            float d = (dx * dx + dy * dy) + dz * dz;
            float nd = fminf(dist[i], d);
            dist[i] = nd;
            if (nd > bv) { bv = nd; bi = (unsigned)(tid + i * 512); }
        }
        unsigned vb = __float_as_uint(bv);
        unsigned wmax = __reduce_max_sync(FULLMASK, vb);
        unsigned cand = (vb == wmax) ? bi : 0xffffffffu;
        unsigned widx = __reduce_min_sync(FULLMASK, cand);
        int par = s & 1;
        if (lane == 0)
            pb[par * 16 + warp] =
                ((unsigned long long)wmax << 32) |
                (unsigned long long)(0xffffffffu - widx);
        __syncthreads();
        unsigned long long k = pb[par * 16 + (lane & 15)];
        unsigned kv = (unsigned)(k >> 32);
        unsigned bmax = __reduce_max_sync(FULLMASK, kv);
        unsigned enc = (kv == bmax) ? (unsigned)k : 0u;
        unsigned benc = __reduce_max_sync(FULLMASK, enc);
        last = (int)(0xffffffffu - benc);
    }
}

// ===== KNN v5: unsorted top-32 + REDUX max-key, 64-pt tiles, 1024 thr =====
__global__ __launch_bounds__(1024) void knn_kernel(const float* __restrict__ x) {
    int b    = blockIdx.x >> 2;
    int part = blockIdx.x & 3;
    extern __shared__ float smk[];
    float* sx0 = smk;
    float* sx1 = smk + 4096;
    float* sx2 = smk + 8192;
    float* sxs = smk + 12288;

    const float* xb = x + (size_t)b * N_ * 3;
    for (int i = threadIdx.x; i < N_; i += 1024) {
        float a0 = xb[i * 3 + 0], a1 = xb[i * 3 + 1], a2 = xb[i * 3 + 2];
        sx0[i] = a0; sx1[i] = a1; sx2[i] = a2;
        sxs[i] = (a0 * a0 + a1 * a1) + a2 * a2;
    }
    __syncthreads();

    int warp = threadIdx.x >> 5, lane = threadIdx.x & 31;
    for (int jj = 0; jj < 4; ++jj) {
        int s  = part * 128 + jj * 32 + warp;
        int bs = b * S_ + s;
        float c0 = g_centroid[bs * 3 + 0];
        float c1 = g_centroid[bs * 3 + 1];
        float c2 = g_centroid[bs * 3 + 2];
        float cs = (c0 * c0 + c1 * c1) + c2 * c2;

        unsigned lb, li, mb, mi;
        {
            int n = lane;
            float dot = (c0 * sx0[n] + c1 * sx1[n]) + c2 * sx2[n];
            float d2  = (cs + sxs[n]) - 2.0f * dot;
            lb = ford(d2);
            li = (unsigned)n;
            mb = __reduce_max_sync(FULLMASK, lb);
            mi = __reduce_max_sync(FULLMASK, (lb == mb) ? li : 0u);
        }
        {
            int n = 32 + lane;
            float dot = (c0 * sx0[n] + c1 * sx1[n]) + c2 * sx2[n];
            float d2  = (cs + sxs[n]) - 2.0f * dot;
            unsigned db = ford(d2);
            bool cand = (db < mb) || (db == mb && (unsigned)n < mi);
            unsigned m = __ballot_sync(FULLMASK, cand);
            while (m) {
                int src = __ffs(m) - 1;
                m &= m - 1;
                unsigned cdb = __shfl_sync(FULLMASK, db, src);
                unsigned cn  = (unsigned)(32 + src);
                if (cdb < mb || (cdb == mb && cn < mi)) {
                    if (lb == mb && li == mi) { lb = cdb; li = cn; }
                    mb = __reduce_max_sync(FULLMASK, lb);
                    mi = __reduce_max_sync(FULLMASK, (lb == mb) ? li : 0u);
                }
            }
        }
        for (int base = 64; base < N_; base += 64) {
            int n1 = base + lane, n2 = n1 + 32;
            float dot1 = (c0 * sx0[n1] + c1 * sx1[n1]) + c2 * sx2[n1];
            float d21  = (cs + sxs[n1]) - 2.0f * dot1;
            float dot2 = (c0 * sx0[n2] + c1 * sx1[n2]) + c2 * sx2[n2];
            float d22  = (cs + sxs[n2]) - 2.0f * dot2;
            unsigned db1 = ford(d21), db2 = ford(d22);
            bool c1f = (db1 < mb) || (db1 == mb && (unsigned)n1 < mi);
            bool c2f = (db2 < mb) || (db2 == mb && (unsigned)n2 < mi);
            unsigned m1 = __ballot_sync(FULLMASK, c1f);
            unsigned m2 = __ballot_sync(FULLMASK, c2f);
            while (m1) {
                int src = __ffs(m1) - 1;
                m1 &= m1 - 1;
                unsigned cdb = __shfl_sync(FULLMASK, db1, src);
                unsigned cn  = (unsigned)(base + src);
                if (cdb < mb || (cdb == mb && cn < mi)) {
                    if (lb == mb && li == mi) { lb = cdb; li = cn; }
                    mb = __reduce_max_sync(FULLMASK, lb);
                    mi = __reduce_max_sync(FULLMASK, (lb == mb) ? li : 0u);
                }
            }
            while (m2) {
                int src = __ffs(m2) - 1;
                m2 &= m2 - 1;
                unsigned cdb = __shfl_sync(FULLMASK, db2, src);
                unsigned cn  = (unsigned)(base + 32 + src);
                if (cdb < mb || (cdb == mb && cn < mi)) {
                    if (lb == mb && li == mi) { lb = cdb; li = cn; }
                    mb = __reduce_max_sync(FULLMASK, lb);
                    mi = __reduce_max_sync(FULLMASK, (lb == mb) ? li : 0u);
                }
            }
        }
        float* gp = g_groups + (size_t)bs * 96;
        int idx = (int)li;
        gp[lane]      = sx0[idx] - c0;
        gp[32 + lane] = sx1[idx] - c1;
        gp[64 + lane] = sx2[idx] - c2;
    }
}

// ========= per-group compute: 2 groups / iteration, 1024 threads ==========
#define PBh_   0
#define PBl_   2304
#define WVh_   4608
#define WVl_   6912
#define WG1h_  9216
#define WG1l_  11520
#define WG2h_  13824
#define WG2l_  16128
#define WA_    18432
#define WQKB_  18624
#define BV_    18752
#define BG1_   18816
#define BG2_   18880
#define BA_    18944
#define BNM_   19008
#define BNR_   19072
#define BNG_   19136
#define BNB_   19200
#define CB_    19264
#define H32_   19272
#define Hh_    23624
#define Hl_    25928
#define Uh_    28232
#define Ul_    30536
#define Vh_    32840
#define Vl_    35144
#define ATTh_  37448
#define ATTl_  38728
#define Th_    40008
#define Tl_    42312
#define G1h_   44616
#define G1l_   46920
#define LG_    49224
#define RBs_   51336
#define CAs_   51400
#define MP_    51464
#define SMTOT  51720
#define SCRQ_  19272
#define SCRK_  23368
#define SCRP_  27464

__global__ __launch_bounds__(1024) void group_kernel(
    const float* __restrict__ w_alpha, const float* __restrict__ b_alpha,
    const float* __restrict__ bn_gamma, const float* __restrict__ bn_beta,
    const float* __restrict__ bn_mean,  const float* __restrict__ bn_var,
    const float* __restrict__ w_q, const float* __restrict__ b_q,
    const float* __restrict__ w_k, const float* __restrict__ b_k,
    const float* __restrict__ w_v, const float* __restrict__ b_v,
    const float* __restrict__ w_g1, const float* __restrict__ b_g1,
    const float* __restrict__ w_g2, const float* __restrict__ b_g2,
    float* __restrict__ out) {
    extern __shared__ float sm[];
    unsigned* su = (unsigned*)sm;
    int tid = threadIdx.x;
    int warp = tid >> 5, lane = tid & 31;
    int qg = lane >> 2, t4 = lane & 3;

    // ---- init phase 1 ----
    for (int i = tid; i < 4096; i += 1024) {
        sm[SCRQ_ + i] = w_q[i];
        sm[SCRK_ + i] = w_k[i];
    }
    for (int i = tid; i < 2048; i += 1024) {
        int d = i >> 5, cp = i & 31;
        int i0 = d * 64 + 2 * cp;
        unsigned short h0, l0, h1, l1;
        bsplit(w_v[i0], h0, l0); bsplit(w_v[i0 + 1], h1, l1);
        su[WVh_ + cp * 72 + d] = pk16(h0, h1);
        su[WVl_ + cp * 72 + d] = pk16(l0, l1);
        bsplit(w_g1[i0], h0, l0); bsplit(w_g1[i0 + 1], h1, l1);
        su[WG1h_ + cp * 72 + d] = pk16(h0, h1);
        su[WG1l_ + cp * 72 + d] = pk16(l0, l1);
        bsplit(w_g2[i0], h0, l0); bsplit(w_g2[i0 + 1], h1, l1);
        su[WG2h_ + cp * 72 + d] = pk16(h0, h1);
        su[WG2l_ + cp * 72 + d] = pk16(l0, l1);
    }
    if (tid < 64) {
        sm[BV_ + tid] = b_v[tid];
        sm[BG1_ + tid] = b_g1[tid]; sm[BG2_ + tid] = b_g2[tid];
        sm[BA_ + tid] = b_alpha[tid];
        sm[BNM_ + tid] = bn_mean[tid];
        sm[BNR_ + tid] = rsqrtf(bn_var[tid] + 1e-5f);
        sm[BNG_ + tid] = bn_gamma[tid];
        sm[BNB_ + tid] = bn_beta[tid];
    }
    __syncthreads();

    // ---- init phase 2 ----
    for (int i = tid; i < 4096; i += 1024) {
        int c = i & 63, cc = i >> 6;
        float s = 0.f;
#pragma unroll 8
        for (int d = 0; d < 64; ++d)
            s += sm[SCRQ_ + d * 64 + c] * sm[SCRK_ + d * 64 + cc];
        sm[SCRP_ + cc * 64 + c] = s;
    }
    if (tid < 192) {
        int d = tid / 3, c = tid % 3;
        float sc = sm[BNR_ + d] * sm[BNG_ + d];
        sm[WA_ + c * 64 + d] = w_alpha[tid] * sc;
    }
    if (tid >= 192 && tid < 256) {
        int d = tid - 192;
        float sc = sm[BNR_ + d] * sm[BNG_ + d];
        float sh = sm[BNB_ + d] - sm[BNM_ + d] * sc;
        sm[BA_ + d] = sm[BA_ + d] * sc + sh;
    }
    if (tid >= 256 && tid < 320) {
        int c = tid - 256;
        float aq = 0.f, ak = 0.f;
#pragma unroll 8
        for (int d = 0; d < 64; ++d) {
            aq += sm[SCRQ_ + d * 64 + c] * b_k[d];
            ak += sm[SCRK_ + d * 64 + c] * b_q[d];
        }
        sm[WQKB_ + 2 * c]     = ak;
        sm[WQKB_ + 2 * c + 1] = aq;
    }
    if (tid == 511) {
        float s = 0.f;
        for (int d = 0; d < 64; ++d) s += b_q[d] * b_k[d];
        sm[CB_] = s;
    }
    __syncthreads();

    // ---- init phase 3 ----
    for (int i = tid; i < 2048; i += 1024) {
        int ccp = i >> 6, c = i & 63;
        unsigned short h0, l0, h1, l1;
        bsplit(sm[SCRP_ + (2 * ccp) * 64 + c], h0, l0);
        bsplit(sm[SCRP_ + (2 * ccp + 1) * 64 + c], h1, l1);
        su[PBh_ + ccp * 72 + c] = pk16(h0, h1);
        su[PBl_ + ccp * 72 + c] = pk16(l0, l1);
    }
    __syncthreads();

    int rt = warp >> 3, nt = warp & 7;        // tile map for B/D/E/F
    int agrp = warp & 1, ad4 = (warp >> 1) * 4;

    for (int p = blockIdx.x; p < B_ * S_ / 2; p += gridDim.x) {
        // ---- A: h = gelu(W_alpha g + b_fold), 4 d per warp ----
        {
            const float* gp = g_groups + ((size_t)(2 * p + agrp)) * 96;
            float gc0 = __ldg(gp + lane);
            float gc1 = __ldg(gp + 32 + lane);
            float gc2 = __ldg(gp + 64 + lane);
            int row = agrp * 32 + lane;
            float hv[4];
#pragma unroll
            for (int r = 0; r < 4; ++r) {
                int d = ad4 + r;
                float v = sm[WA_ + d] * gc0 + sm[WA_ + 64 + d] * gc1 +
                          sm[WA_ + 128 + d] * gc2 + sm[BA_ + d];
                v = gelu_exact(v);
                hv[r] = v;
                sm[H32_ + d * 68 + row] = v;
            }
            unsigned short h0, l0, h1, l1;
            bsplit(hv[0], h0, l0); bsplit(hv[1], h1, l1);
            int kp = ad4 >> 1;
            su[Hh_ + row * 36 + kp] = pk16(h0, h1);
            su[Hl_ + row * 36 + kp] = pk16(l0, l1);
            bsplit(hv[2], h0, l0); bsplit(hv[3], h1, l1);
            su[Hh_ + row * 36 + kp + 1] = pk16(h0, h1);
            su[Hl_ + row * 36 + kp + 1] = pk16(l0, l1);
        }
        __syncthreads();

        // ---- B: u = P h ; v = Wv h + bv  (one m16n8 tile per warp) ----
        {
            int n0 = nt * 8 + qg;
            int ra0 = rt * 16 + qg, ra1 = ra0 + 8;
            float uh[4] = {0, 0, 0, 0}, ue[4] = {0, 0, 0, 0};
            float vh[4] = {0, 0, 0, 0}, ve[4] = {0, 0, 0, 0};
#pragma unroll
            for (int kt = 0; kt < 4; ++kt) {
                int kp0 = kt * 8 + t4, kp1 = kp0 + 4;
                unsigned ah[4], al[4];
                ah[0] = su[Hh_ + ra0 * 36 + kp0];
                ah[1] = su[Hh_ + ra1 * 36 + kp0];
                ah[2] = su[Hh_ + ra0 * 36 + kp1];
                ah[3] = su[Hh_ + ra1 * 36 + kp1];
                al[0] = su[Hl_ + ra0 * 36 + kp0];
                al[1] = su[Hl_ + ra1 * 36 + kp0];
                al[2] = su[Hl_ + ra0 * 36 + kp1];
                al[3] = su[Hl_ + ra1 * 36 + kp1];
                unsigned bh0 = su[PBh_ + kp0 * 72 + n0];
                unsigned bh1 = su[PBh_ + kp1 * 72 + n0];
                unsigned bl0 = su[PBl_ + kp0 * 72 + n0];
                unsigned bl1 = su[PBl_ + kp1 * 72 + n0];
                mma16(uh, ah, bh0, bh1);
                mma16(ue, ah, bl0, bl1);
                mma16(ue, al, bh0, bh1);
                bh0 = su[WVh_ + kp0 * 72 + n0];
                bh1 = su[WVh_ + kp1 * 72 + n0];
                bl0 = su[WVl_ + kp0 * 72 + n0];
                bl1 = su[WVl_ + kp1 * 72 + n0];
                mma16(vh, ah, bh0, bh1);
                mma16(ve, ah, bl0, bl1);
                mma16(ve, al, bh0, bh1);
            }
            int cc0 = nt * 8 + 2 * t4, cc1 = cc0 + 1;
            float bv0 = sm[BV_ + cc0], bv1 = sm[BV_ + cc1];
            int kpU = nt * 4 + t4;
            float u0 = uh[0] + ue[0], u1 = uh[1] + ue[1];
            float u2 = uh[2] + ue[2], u3 = uh[3] + ue[3];
            float v0 = vh[0] + ve[0] + bv0, v1 = vh[1] + ve[1] + bv1;
            float v2 = vh[2] + ve[2] + bv0, v3 = vh[3] + ve[3] + bv1;
            unsigned short h0, l0, h1, l1;
            bsplit(u0, h0, l0); bsplit(u1, h1, l1);
            su[Uh_ + kpU * 72 + ra0] = pk16(h0, h1);
            su[Ul_ + kpU * 72 + ra0] = pk16(l0, l1);
            bsplit(u2, h0, l0); bsplit(u3, h1, l1);
            su[Uh_ + kpU * 72 + ra1] = pk16(h0, h1);
            su[Ul_ + kpU * 72 + ra1] = pk16(l0, l1);
            unsigned s0 = bsplitw(v0), s1 = bsplitw(v1);
            unsigned s2 = bsplitw(v2), s3 = bsplitw(v3);
            unsigned p0 = __shfl_xor_sync(FULLMASK, s0, 4);
            unsigned p1 = __shfl_xor_sync(FULLMASK, s1, 4);
            unsigned p2 = __shfl_xor_sync(FULLMASK, s2, 4);
            unsigned p3 = __shfl_xor_sync(FULLMASK, s3, 4);
            if ((qg & 1) == 0) {
                int kv0 = rt * 8 + (qg >> 1);
                int kv1 = kv0 + 4;
                su[Vh_ + kv0 * 72 + cc0] = __byte_perm(s0, p0, 0x5410);
                su[Vl_ + kv0 * 72 + cc0] = __byte_perm(s0, p0, 0x7632);
                su[Vh_ + kv0 * 72 + cc1] = __byte_perm(s1, p1, 0x5410);
                su[Vl_ + kv0 * 72 + cc1] = __byte_perm(s1, p1, 0x7632);
                su[Vh_ + kv1 * 72 + cc0] = __byte_perm(s2, p2, 0x5410);
                su[Vl_ + kv1 * 72 + cc0] = __byte_perm(s2, p2, 0x7632);
                su[Vh_ + kv1 * 72 + cc1] = __byte_perm(s3, p3, 0x5410);
                su[Vl_ + kv1 * 72 + cc1] = __byte_perm(s3, p3, 0x7632);
            }
        }
        if (warp < 2) {
            int grp = warp;
            unsigned long long rc = 0;
#pragma unroll 8
            for (int cc = 0; cc < 64; ++cc) {
                float hv = sm[H32_ + cc * 68 + grp * 32 + lane];
                rc = fma2_(*(const unsigned long long*)&sm[WQKB_ + 2 * cc],
                           pk2(hv, hv), rc);
            }
            float rB, cA;
            upk2(rc, rB, cA);
            sm[RBs_ + grp * 32 + lane] = rB;
            sm[CAs_ + grp * 32 + lane] = cA;
        }
        __syncthreads();

        // ---- C: logits = h^T u  (warps 0..15) ----
        if (warp < 16) {
            int grp = warp >> 3, cmt = (warp >> 2) & 1, cnt = warp & 3;
            int ra0 = grp * 32 + cmt * 16 + qg, ra1 = ra0 + 8;
            int n0 = grp * 32 + cnt * 8 + qg;
            float ch[4] = {0, 0, 0, 0}, ce[4] = {0, 0, 0, 0};
#pragma unroll
            for (int kt = 0; kt < 4; ++kt) {
                int kp0 = kt * 8 + t4, kp1 = kp0 + 4;
                unsigned ah[4], al[4];
                ah[0] = su[Hh_ + ra0 * 36 + kp0];
                ah[1] = su[Hh_ + ra1 * 36 + kp0];
                ah[2] = su[Hh_ + ra0 * 36 + kp1];
                ah[3] = su[Hh_ + ra1 * 36 + kp1];
                al[0] = su[Hl_ + ra0 * 36 + kp0];
                al[1] = su[Hl_ + ra1 * 36 + kp0];
                al[2] = su[Hl_ + ra0 * 36 + kp1];
                al[3] = su[Hl_ + ra1 * 36 + kp1];
                unsigned bh0 = su[Uh_ + kp0 * 72 + n0];
                unsigned bh1 = su[Uh_ + kp1 * 72 + n0];
                unsigned bl0 = su[Ul_ + kp0 * 72 + n0];
                unsigned bl1 = su[Ul_ + kp1 * 72 + n0];
                mma16(ch, ah, bh0, bh1);
                mma16(ce, ah, bl0, bl1);
                mma16(ce, al, bh0, bh1);
            }
            int jc0 = cnt * 8 + 2 * t4;
            sm[LG_ + ra0 * 33 + jc0]     = ch[0] + ce[0];
            sm[LG_ + ra0 * 33 + jc0 + 1] = ch[1] + ce[1];
            sm[LG_ + ra1 * 33 + jc0]     = ch[2] + ce[2];
            sm[LG_ + ra1 * 33 + jc0 + 1] = ch[3] + ce[3];
        }
        __syncthreads();

        // ---- softmax: 2 rows per warp ----
        {
            float cb = sm[CB_];
#pragma unroll
            for (int k = 0; k < 2; ++k) {
                int r = warp + 32 * k;
                int grp = r >> 5, i = r & 31;
                float a = (sm[LG_ + r * 33 + lane] + sm[CAs_ + grp * 32 + i] +
                           sm[RBs_ + grp * 32 + lane] + cb) * 0.125f;
                float m = a;
#pragma unroll
                for (int off = 16; off; off >>= 1)
                    m = fmaxf(m, __shfl_xor_sync(FULLMASK, m, off));
                float e = expf(a - m);
                float s = e;
#pragma unroll
                for (int off = 16; off; off >>= 1)
                    s += __shfl_xor_sync(FULLMASK, s, off);
                float pf = e / s;
                unsigned w0 = bsplitw(pf);
                unsigned q0 = __shfl_xor_sync(FULLMASK, w0, 1);
                if ((lane & 1) == 0) {
                    int jp = lane >> 1;
                    su[ATTh_ + r * 20 + jp] = __byte_perm(w0, q0, 0x5410);
                    su[ATTl_ + r * 20 + jp] = __byte_perm(w0, q0, 0x7632);
                }
            }
        }
        __syncthreads();

        // ---- D: res = attn v ; T = res + h (tile = F's tile) ----
        float rr[4];
        {
            int grp = rt >> 1;
            int n0 = nt * 8 + qg;
            int dc0 = nt * 8 + 2 * t4, dc1 = dc0 + 1;
            int kpT = nt * 4 + t4;
            int ra0 = rt * 16 + qg, ra1 = ra0 + 8;
            float rh[4] = {0, 0, 0, 0}, re[4] = {0, 0, 0, 0};
#pragma unroll
            for (int kt = 0; kt < 2; ++kt) {
                int kp0 = kt * 8 + t4, kp1 = kp0 + 4;
                unsigned ah[4], al[4];
                ah[0] = su[ATTh_ + ra0 * 20 + kp0];
                ah[1] = su[ATTh_ + ra1 * 20 + kp0];
                ah[2] = su[ATTh_ + ra0 * 20 + kp1];
                ah[3] = su[ATTh_ + ra1 * 20 + kp1];
                al[0] = su[ATTl_ + ra0 * 20 + kp0];
                al[1] = su[ATTl_ + ra1 * 20 + kp0];
                al[2] = su[ATTl_ + ra0 * 20 + kp1];
                al[3] = su[ATTl_ + ra1 * 20 + kp1];
                int kg0 = grp * 16 + kp0, kg1 = grp * 16 + kp1;
                unsigned bh0 = su[Vh_ + kg0 * 72 + n0];
                unsigned bh1 = su[Vh_ + kg1 * 72 + n0];
                unsigned bl0 = su[Vl_ + kg0 * 72 + n0];
                unsigned bl1 = su[Vl_ + kg1 * 72 + n0];
                mma16(rh, ah, bh0, bh1);
                mma16(re, ah, bl0, bl1);
                mma16(re, al, bh0, bh1);
            }
            rr[0] = rh[0] + re[0]; rr[1] = rh[1] + re[1];
            rr[2] = rh[2] + re[2]; rr[3] = rh[3] + re[3];
            float t0 = rr[0] + sm[H32_ + dc0 * 68 + ra0];
            float t1 = rr[1] + sm[H32_ + dc1 * 68 + ra0];
            float t2 = rr[2] + sm[H32_ + dc0 * 68 + ra1];
            float t3 = rr[3] + sm[H32_ + dc1 * 68 + ra1];
            unsigned short h0, l0, h1, l1;
            bsplit(t0, h0, l0); bsplit(t1, h1, l1);
            su[Th_ + ra0 * 36 + kpT] = pk16(h0, h1);
            su[Tl_ + ra0 * 36 + kpT] = pk16(l0, l1);
            bsplit(t2, h0, l0); bsplit(t3, h1, l1);
            su[Th_ + ra1 * 36 + kpT] = pk16(h0, h1);
            su[Tl_ + ra1 * 36 + kpT] = pk16(l0, l1);
        }
        __syncthreads();

        // ---- E: G1 = gelu(Wg1 T + bg1) ----
        {
            int n0 = nt * 8 + qg;
            int dc0 = nt * 8 + 2 * t4, dc1 = dc0 + 1;
            float b0 = sm[BG1_ + dc0], b1 = sm[BG1_ + dc1];
            int kpT = nt * 4 + t4;
            int ra0 = rt * 16 + qg, ra1 = ra0 + 8;
            float gh[4] = {0, 0, 0, 0}, ge[4] = {0, 0, 0, 0};
#pragma unroll
            for (int kt = 0; kt < 4; ++kt) {
                int kp0 = kt * 8 + t4, kp1 = kp0 + 4;
                unsigned ah[4], al[4];
                ah[0] = su[Th_ + ra0 * 36 + kp0];
                ah[1] = su[Th_ + ra1 * 36 + kp0];
                ah[2] = su[Th_ + ra0 * 36 + kp1];
                ah[3] = su[Th_ + ra1 * 36 + kp1];
                al[0] = su[Tl_ + ra0 * 36 + kp0];
                al[1] = su[Tl_ + ra1 * 36 + kp0];
                al[2] = su[Tl_ + ra0 * 36 + kp1];
                al[3] = su[Tl_ + ra1 * 36 + kp1];
                unsigned bh0 = su[WG1h_ + kp0 * 72 + n0];
                unsigned bh1 = su[WG1h_ + kp1 * 72 + n0];
                unsigned bl0 = su[WG1l_ + kp0 * 72 + n0];
                unsigned bl1 = su[WG1l_ + kp1 * 72 + n0];
                mma16(gh, ah, bh0, bh1);
                mma16(ge, ah, bl0, bl1);
                mma16(ge, al, bh0, bh1);
            }
            float g0 = gelu_exact(gh[0] + ge[0] + b0);
            float g1 = gelu_exact(gh[1] + ge[1] + b1);
            float g2 = gelu_exact(gh[2] + ge[2] + b0);
            float g3 = gelu_exact(gh[3] + ge[3] + b1);
            unsigned short h0, l0, h1, l1;
            bsplit(g0, h0, l0); bsplit(g1, h1, l1);
            su[G1h_ + ra0 * 36 + kpT] = pk16(h0, h1);
            su[G1l_ + ra0 * 36 + kpT] = pk16(l0, l1);
            bsplit(g2, h0, l0); bsplit(g3, h1, l1);
            su[G1h_ + ra1 * 36 + kpT] = pk16(h0, h1);
            su[G1l_ + ra1 * 36 + kpT] = pk16(l0, l1);
        }
        __syncthreads();

        // ---- F: out = Wg2 G1 + bg2 + res ; maxpool ----
        {
            int grp = rt >> 1, half = rt & 1;
            int n0 = nt * 8 + qg;
            int dc0 = nt * 8 + 2 * t4, dc1 = dc0 + 1;
            float b0 = sm[BG2_ + dc0], b1 = sm[BG2_ + dc1];
            int ra0 = rt * 16 + qg, ra1 = ra0 + 8;
            float fh[4] = {0, 0, 0, 0}, fe[4] = {0, 0, 0, 0};
#pragma unroll
            for (int kt = 0; kt < 4; ++kt) {
                int kp0 = kt * 8 + t4, kp1 = kp0 + 4;
                unsigned ah[4], al[4];
                ah[0] = su[G1h_ + ra0 * 36 + kp0];
                ah[1] = su[G1h_ + ra1 * 36 + kp0];
                ah[2] = su[G1h_ + ra0 * 36 + kp1];
                ah[3] = su[G1h_ + ra1 * 36 + kp1];
                al[0] = su[G1l_ + ra0 * 36 + kp0];
                al[1] = su[G1l_ + ra1 * 36 + kp0];
                al[2] = su[G1l_ + ra0 * 36 + kp1];
                al[3] = su[G1l_ + ra1 * 36 + kp1];
                unsigned bh0 = su[WG2h_ + kp0 * 72 + n0];
                unsigned bh1 = su[WG2h_ + kp1 * 72 + n0];
                unsigned bl0 = su[WG2l_ + kp0 * 72 + n0];
                unsigned bl1 = su[WG2l_ + kp1 * 72 + n0];
                mma16(fh, ah, bh0, bh1);
                mma16(fe, ah, bl0, bl1);
                mma16(fe, al, bh0, bh1);
            }
            float v0 = fh[0] + fe[0] + b0 + rr[0];
            float v1 = fh[1] + fe[1] + b1 + rr[1];
            float v2 = fh[2] + fe[2] + b0 + rr[2];
            float v3 = fh[3] + fe[3] + b1 + rr[3];
            float m0 = fmaxf(v0, v2), m1 = fmaxf(v1, v3);
#pragma unroll
            for (int off = 4; off < 32; off <<= 1) {
                m0 = fmaxf(m0, __shfl_xor_sync(FULLMASK, m0, off));
                m1 = fmaxf(m1, __shfl_xor_sync(FULLMASK, m1, off));
            }
            if (lane < 4) {
                sm[MP_ + grp * 128 + half * 64 + nt * 8 + 2 * t4]     = m0;
                sm[MP_ + grp * 128 + half * 64 + nt * 8 + 2 * t4 + 1] = m1;
            }
        }
        __syncthreads();
        if (tid < 128) {
            int grp = tid >> 6, d = tid & 63;
            out[(size_t)(2 * p + grp) * 67 + 3 + d] =
                fmaxf(sm[MP_ + grp * 128 + d], sm[MP_ + grp * 128 + 64 + d]);
        }
        __syncthreads();
    }
}

// ============================ launch ======================================
extern "C" void kernel_launch(void* const* d_in, const int* in_sizes, int n_in,
                              void* d_out, int out_size) {
    (void)in_sizes; (void)n_in; (void)out_size;
    const float* x        = (const float*)d_in[0];
    const float* w_alpha  = (const float*)d_in[1];
    const float* b_alpha  = (const float*)d_in[2];
    const float* bn_gamma = (const float*)d_in[3];
    const float* bn_beta  = (const float*)d_in[4];
    const float* bn_mean  = (const float*)d_in[5];
    const float* bn_var   = (const float*)d_in[6];
    const float* w_q      = (const float*)d_in[7];
    const float* b_q      = (const float*)d_in[8];
    const float* w_k      = (const float*)d_in[9];
    const float* b_k      = (const float*)d_in[10];
    const float* w_v      = (const float*)d_in[11];
    const float* b_v      = (const float*)d_in[12];
    const float* w_g1     = (const float*)d_in[13];
    const float* b_g1     = (const float*)d_in[14];
    const float* w_g2     = (const float*)d_in[15];
    const float* b_g2     = (const float*)d_in[16];
    float* out = (float*)d_out;

    cudaFuncSetAttribute(fps_kernel,
                         cudaFuncAttributeMaxDynamicSharedMemorySize, 49664);
    cudaFuncSetAttribute(knn_kernel,
                         cudaFuncAttributeMaxDynamicSharedMemorySize, 65536);
    cudaFuncSetAttribute(group_kernel,
                         cudaFuncAttributeMaxDynamicSharedMemorySize, SMTOT * 4);

    fps_kernel<<<B_, 512, 49664>>>(x, out);
    knn_kernel<<<B_ * 4, 1024, 65536>>>(x);
    group_kernel<<<148, 1024, SMTOT * 4>>>(w_alpha, b_alpha, bn_gamma, bn_beta,
                                           bn_mean, bn_var, w_q, b_q, w_k, b_k,
                                           w_v, b_v, w_g1, b_g1, w_g2, b_g2, out);
}

// round 16
// speedup vs baseline: 3.4964x; 1.0142x over previous
#include <cuda_runtime.h>
#include <math.h>

#define B_   32
#define N_   4096
#define S_   512
#define FULLMASK 0xffffffffu

__device__ float g_centroid[B_ * S_ * 3];
__device__ float g_groups[B_ * S_ * 96];   // [bs][c][k]

// ---------------- helpers -------------------------------------------------
__device__ __forceinline__ unsigned long long pk2(float lo, float hi) {
    unsigned long long r;
    asm("mov.b64 %0, {%1, %2};" : "=l"(r) : "f"(lo), "f"(hi));
    return r;
}
__device__ __forceinline__ void upk2(unsigned long long v, float& lo, float& hi) {
    asm("mov.b64 {%0, %1}, %2;" : "=f"(lo), "=f"(hi) : "l"(v));
}
__device__ __forceinline__ unsigned long long fma2_(unsigned long long a,
                                                   unsigned long long b,
                                                   unsigned long long c) {
    unsigned long long d;
    asm("fma.rn.f32x2 %0, %1, %2, %3;" : "=l"(d) : "l"(a), "l"(b), "l"(c));
    return d;
}
__device__ __forceinline__ unsigned short bh16(float x) {
    unsigned short r;
    asm("cvt.rn.bf16.f32 %0, %1;" : "=h"(r) : "f"(x));
    return r;
}
__device__ __forceinline__ float bf2f(unsigned short h) {
    return __uint_as_float((unsigned)h << 16);
}
__device__ __forceinline__ void bsplit(float x, unsigned short& h, unsigned short& l) {
    h = bh16(x);
    l = bh16(x - bf2f(h));
}
__device__ __forceinline__ unsigned pk16(unsigned short a, unsigned short b) {
    return (unsigned)a | ((unsigned)b << 16);
}
__device__ __forceinline__ unsigned bsplitw(float x) {
    unsigned short h, l;
    bsplit(x, h, l);
    return pk16(h, l);
}
__device__ __forceinline__ unsigned ford(float x) {
    unsigned b = __float_as_uint(x);
    return b ^ (((int)b >> 31) | 0x80000000u);
}
__device__ __forceinline__ void mma16(float* c, const unsigned* a,
                                      unsigned b0, unsigned b1) {
    asm("mma.sync.aligned.m16n8k16.row.col.f32.bf16.bf16.f32 "
        "{%0,%1,%2,%3},{%4,%5,%6,%7},{%8,%9},{%0,%1,%2,%3};"
        : "+f"(c[0]), "+f"(c[1]), "+f"(c[2]), "+f"(c[3])
        : "r"(a[0]), "r"(a[1]), "r"(a[2]), "r"(a[3]), "r"(b0), "r"(b1));
}
__device__ __forceinline__ float gelu_exact(float v) {
    return 0.5f * v * (1.0f + erff(v * 0.70710678118654752440f));
}

// ============================ FPS (512 thr, 8 pts/thr) ====================
__global__ __launch_bounds__(512) void fps_kernel(const float* __restrict__ x,
                                                  float* __restrict__ out) {
    extern __shared__ float smf[];
    float* sx0 = smf;
    float* sx1 = smf + 4096;
    float* sx2 = smf + 8192;
    unsigned long long* pb = (unsigned long long*)(smf + 12288);

    int b = blockIdx.x, tid = threadIdx.x;
    int lane = tid & 31, warp = tid >> 5;
    const float* xb = x + (size_t)b * N_ * 3;

    float px[8], py[8], pz[8], dist[8];
#pragma unroll
    for (int i = 0; i < 8; ++i) {
        int n = tid + i * 512;
        float a0 = xb[n * 3 + 0], a1 = xb[n * 3 + 1], a2 = xb[n * 3 + 2];
        px[i] = a0; py[i] = a1; pz[i] = a2;
        sx0[n] = a0; sx1[n] = a1; sx2[n] = a2;
        dist[i] = 1e10f;
    }
    __syncthreads();

    int last = 0;
    for (int s = 0; s < S_; ++s) {
        float c0 = sx0[last], c1 = sx1[last], c2 = sx2[last];
        if (tid == 0) {
            int bs = b * S_ + s;
            out[(size_t)bs * 67 + 0] = c0;
            out[(size_t)bs * 67 + 1] = c1;
            out[(size_t)bs * 67 + 2] = c2;
            g_centroid[bs * 3 + 0] = c0;
            g_centroid[bs * 3 + 1] = c1;
            g_centroid[bs * 3 + 2] = c2;
        }
#pragma unroll
        for (int i = 0; i < 8; ++i) {
            float dx = px[i] - c0, dy = py[i] - c1, dz = pz[i] - c2;
            float d = (dx * dx + dy * dy) + dz * dz;
            dist[i] = fminf(dist[i], d);
        }
        // value-max via tree (exact), index recovered post-REDUX
        float m01 = fmaxf(dist[0], dist[1]), m23 = fmaxf(dist[2], dist[3]);
        float m45 = fmaxf(dist[4], dist[5]), m67 = fmaxf(dist[6], dist[7]);
        float m03 = fmaxf(m01, m23), m47 = fmaxf(m45, m67);
        float bv = fmaxf(m03, m47);
        unsigned vb = __float_as_uint(bv);
        unsigned wmax = __reduce_max_sync(FULLMASK, vb);
        unsigned bi = 0xffffffffu;
#pragma unroll
        for (int i = 0; i < 8; ++i)
            if (__float_as_uint(dist[i]) == wmax)
                bi = min(bi, (unsigned)(tid + i * 512));
        unsigned widx = __reduce_min_sync(FULLMASK, bi);
        int par = s & 1;
        if (lane == 0)
            pb[par * 16 + warp] =
                ((unsigned long long)wmax << 32) |
                (unsigned long long)(0xffffffffu - widx);
        __syncthreads();
        unsigned long long k = pb[par * 16 + (lane & 15)];
        unsigned kv = (unsigned)(k >> 32);
        unsigned bmax = __reduce_max_sync(FULLMASK, kv);
        unsigned enc = (kv == bmax) ? (unsigned)k : 0u;
        unsigned benc = __reduce_max_sync(FULLMASK, enc);
        last = (int)(0xffffffffu - benc);
    }
}

// ===== KNN v5: unsorted top-32 + REDUX max-key, 64-pt tiles, 1024 thr =====
__global__ __launch_bounds__(1024) void knn_kernel(const float* __restrict__ x) {
    int b    = blockIdx.x >> 2;
    int part = blockIdx.x & 3;
    extern __shared__ float smk[];
    float* sx0 = smk;
    float* sx1 = smk + 4096;
    float* sx2 = smk + 8192;
    float* sxs = smk + 12288;

    const float* xb = x + (size_t)b * N_ * 3;
    for (int i = threadIdx.x; i < N_; i += 1024) {
        float a0 = xb[i * 3 + 0], a1 = xb[i * 3 + 1], a2 = xb[i * 3 + 2];
        sx0[i] = a0; sx1[i] = a1; sx2[i] = a2;
        sxs[i] = (a0 * a0 + a1 * a1) + a2 * a2;
    }
    __syncthreads();

    int warp = threadIdx.x >> 5, lane = threadIdx.x & 31;
    for (int jj = 0; jj < 4; ++jj) {
        int s  = part * 128 + jj * 32 + warp;
        int bs = b * S_ + s;
        float c0 = g_centroid[bs * 3 + 0];
        float c1 = g_centroid[bs * 3 + 1];
        float c2 = g_centroid[bs * 3 + 2];
        float cs = (c0 * c0 + c1 * c1) + c2 * c2;

        unsigned lb, li, mb, mi;
        {
            int n = lane;
            float dot = (c0 * sx0[n] + c1 * sx1[n]) + c2 * sx2[n];
            float d2  = (cs + sxs[n]) - 2.0f * dot;
            lb = ford(d2);
            li = (unsigned)n;
            mb = __reduce_max_sync(FULLMASK, lb);
            mi = __reduce_max_sync(FULLMASK, (lb == mb) ? li : 0u);
        }
        {
            int n = 32 + lane;
            float dot = (c0 * sx0[n] + c1 * sx1[n]) + c2 * sx2[n];
            float d2  = (cs + sxs[n]) - 2.0f * dot;
            unsigned db = ford(d2);
            bool cand = (db < mb) || (db == mb && (unsigned)n < mi);
            unsigned m = __ballot_sync(FULLMASK, cand);
            while (m) {
                int src = __ffs(m) - 1;
                m &= m - 1;
                unsigned cdb = __shfl_sync(FULLMASK, db, src);
                unsigned cn  = (unsigned)(32 + src);
                if (cdb < mb || (cdb == mb && cn < mi)) {
                    if (lb == mb && li == mi) { lb = cdb; li = cn; }
                    mb = __reduce_max_sync(FULLMASK, lb);
                    mi = __reduce_max_sync(FULLMASK, (lb == mb) ? li : 0u);
                }
            }
        }
        for (int base = 64; base < N_; base += 64) {
            int n1 = base + lane, n2 = n1 + 32;
            float dot1 = (c0 * sx0[n1] + c1 * sx1[n1]) + c2 * sx2[n1];
            float d21  = (cs + sxs[n1]) - 2.0f * dot1;
            float dot2 = (c0 * sx0[n2] + c1 * sx1[n2]) + c2 * sx2[n2];
            float d22  = (cs + sxs[n2]) - 2.0f * dot2;
            unsigned db1 = ford(d21), db2 = ford(d22);
            bool c1f = (db1 < mb) || (db1 == mb && (unsigned)n1 < mi);
            bool c2f = (db2 < mb) || (db2 == mb && (unsigned)n2 < mi);
            unsigned m1 = __ballot_sync(FULLMASK, c1f);
            unsigned m2 = __ballot_sync(FULLMASK, c2f);
            while (m1) {
                int src = __ffs(m1) - 1;
                m1 &= m1 - 1;
                unsigned cdb = __shfl_sync(FULLMASK, db1, src);
                unsigned cn  = (unsigned)(base + src);
                if (cdb < mb || (cdb == mb && cn < mi)) {
                    if (lb == mb && li == mi) { lb = cdb; li = cn; }
                    mb = __reduce_max_sync(FULLMASK, lb);
                    mi = __reduce_max_sync(FULLMASK, (lb == mb) ? li : 0u);
                }
            }
            while (m2) {
                int src = __ffs(m2) - 1;
                m2 &= m2 - 1;
                unsigned cdb = __shfl_sync(FULLMASK, db2, src);
                unsigned cn  = (unsigned)(base + 32 + src);
                if (cdb < mb || (cdb == mb && cn < mi)) {
                    if (lb == mb && li == mi) { lb = cdb; li = cn; }
                    mb = __reduce_max_sync(FULLMASK, lb);
                    mi = __reduce_max_sync(FULLMASK, (lb == mb) ? li : 0u);
                }
            }
        }
        float* gp = g_groups + (size_t)bs * 96;
        int idx = (int)li;
        gp[lane]      = sx0[idx] - c0;
        gp[32 + lane] = sx1[idx] - c1;
        gp[64 + lane] = sx2[idx] - c2;
    }
}

// ================= per-group compute: 2 groups / iteration ================
#define PBh_   0
#define PBl_   2304
#define WVh_   4608
#define WVl_   6912
#define WG1h_  9216
#define WG1l_  11520
#define WG2h_  13824
#define WG2l_  16128
#define WA_    18432
#define WQKB_  18624
#define BV_    18752
#define BG1_   18816
#define BG2_   18880
#define BA_    18944
#define BNM_   19008
#define BNR_   19072
#define BNG_   19136
#define BNB_   19200
#define CB_    19264
#define H32_   19272
#define Hh_    23624
#define Hl_    25928
#define Uh_    28232
#define Ul_    30536
#define Vh_    32840
#define Vl_    35144
#define ATTh_  37448
#define ATTl_  38728
#define Th_    40008
#define Tl_    42312
#define G1h_   44616
#define G1l_   46920
#define LG_    49224
#define RBs_   51336
#define CAs_   51400
#define MP_    51464
#define SMTOT  51720
#define SCRQ_  19272
#define SCRK_  23368
#define SCRP_  27464

__global__ __launch_bounds__(512) void group_kernel(
    const float* __restrict__ w_alpha, const float* __restrict__ b_alpha,
    const float* __restrict__ bn_gamma, const float* __restrict__ bn_beta,
    const float* __restrict__ bn_mean,  const float* __restrict__ bn_var,
    const float* __restrict__ w_q, const float* __restrict__ b_q,
    const float* __restrict__ w_k, const float* __restrict__ b_k,
    const float* __restrict__ w_v, const float* __restrict__ b_v,
    const float* __restrict__ w_g1, const float* __restrict__ b_g1,
    const float* __restrict__ w_g2, const float* __restrict__ b_g2,
    float* __restrict__ out) {
    extern __shared__ float sm[];
    unsigned* su = (unsigned*)sm;
    int tid = threadIdx.x;
    int warp = tid >> 5, lane = tid & 31;
    int qg = lane >> 2, t4 = lane & 3;

    // ---- init phase 1 ----
    for (int i = tid; i < 4096; i += 512) {
        sm[SCRQ_ + i] = w_q[i];
        sm[SCRK_ + i] = w_k[i];
    }
    for (int i = tid; i < 2048; i += 512) {
        int d = i >> 5, cp = i & 31;
        int i0 = d * 64 + 2 * cp;
        unsigned short h0, l0, h1, l1;
        bsplit(w_v[i0], h0, l0); bsplit(w_v[i0 + 1], h1, l1);
        su[WVh_ + cp * 72 + d] = pk16(h0, h1);
        su[WVl_ + cp * 72 + d] = pk16(l0, l1);
        bsplit(w_g1[i0], h0, l0); bsplit(w_g1[i0 + 1], h1, l1);
        su[WG1h_ + cp * 72 + d] = pk16(h0, h1);
        su[WG1l_ + cp * 72 + d] = pk16(l0, l1);
        bsplit(w_g2[i0], h0, l0); bsplit(w_g2[i0 + 1], h1, l1);
        su[WG2h_ + cp * 72 + d] = pk16(h0, h1);
        su[WG2l_ + cp * 72 + d] = pk16(l0, l1);
    }
    if (tid < 64) {
        sm[BV_ + tid] = b_v[tid];
        sm[BG1_ + tid] = b_g1[tid]; sm[BG2_ + tid] = b_g2[tid];
        sm[BA_ + tid] = b_alpha[tid];
        sm[BNM_ + tid] = bn_mean[tid];
        sm[BNR_ + tid] = rsqrtf(bn_var[tid] + 1e-5f);
        sm[BNG_ + tid] = bn_gamma[tid];
        sm[BNB_ + tid] = bn_beta[tid];
    }
    __syncthreads();

    // ---- init phase 2 ----
    for (int i = tid; i < 4096; i += 512) {
        int c = i & 63, cc = i >> 6;
        float s = 0.f;
#pragma unroll 8
        for (int d = 0; d < 64; ++d)
            s += sm[SCRQ_ + d * 64 + c] * sm[SCRK_ + d * 64 + cc];
        sm[SCRP_ + cc * 64 + c] = s;
    }
    if (tid < 192) {
        int d = tid / 3, c = tid % 3;
        float sc = sm[BNR_ + d] * sm[BNG_ + d];
        sm[WA_ + c * 64 + d] = w_alpha[tid] * sc;
    }
    if (tid >= 192 && tid < 256) {
        int d = tid - 192;
        float sc = sm[BNR_ + d] * sm[BNG_ + d];
        float sh = sm[BNB_ + d] - sm[BNM_ + d] * sc;
        sm[BA_ + d] = sm[BA_ + d] * sc + sh;
    }
    if (tid >= 256 && tid < 320) {
        int c = tid - 256;
        float aq = 0.f, ak = 0.f;
#pragma unroll 8
        for (int d = 0; d < 64; ++d) {
            aq += sm[SCRQ_ + d * 64 + c] * b_k[d];
            ak += sm[SCRK_ + d * 64 + c] * b_q[d];
        }
        sm[WQKB_ + 2 * c]     = ak;
        sm[WQKB_ + 2 * c + 1] = aq;
    }
    if (tid == 511) {
        float s = 0.f;
        for (int d = 0; d < 64; ++d) s += b_q[d] * b_k[d];
        sm[CB_] = s;
    }
    __syncthreads();

    // ---- init phase 3 ----
    for (int i = tid; i < 2048; i += 512) {
        int ccp = i >> 6, c = i & 63;
        unsigned short h0, l0, h1, l1;
        bsplit(sm[SCRP_ + (2 * ccp) * 64 + c], h0, l0);
        bsplit(sm[SCRP_ + (2 * ccp + 1) * 64 + c], h1, l1);
        su[PBh_ + ccp * 72 + c] = pk16(h0, h1);
        su[PBl_ + ccp * 72 + c] = pk16(l0, l1);
    }
    __syncthreads();

    int mt0 = warp >> 3, nt = warp & 7;
    int agrp = warp & 1, ad8 = (warp >> 1) * 8;

    // prefetch first iteration's group coords
    float ngc0 = 0.f, ngc1 = 0.f, ngc2 = 0.f;
    {
        int p0 = blockIdx.x;
        if (p0 < B_ * S_ / 2) {
            const float* gp = g_groups + ((size_t)(2 * p0 + agrp)) * 96;
            ngc0 = __ldg(gp + lane);
            ngc1 = __ldg(gp + 32 + lane);
            ngc2 = __ldg(gp + 64 + lane);
        }
    }

    for (int p = blockIdx.x; p < B_ * S_ / 2; p += gridDim.x) {
        // ---- A ----
        {
            float gc0 = ngc0, gc1 = ngc1, gc2 = ngc2;
            int row = agrp * 32 + lane;
            float hv[8];
#pragma unroll
            for (int r = 0; r < 8; ++r) {
                int d = ad8 + r;
                float v = sm[WA_ + d] * gc0 + sm[WA_ + 64 + d] * gc1 +
                          sm[WA_ + 128 + d] * gc2 + sm[BA_ + d];
                v = gelu_exact(v);
                hv[r] = v;
                sm[H32_ + d * 68 + row] = v;
            }
#pragma unroll
            for (int r = 0; r < 4; ++r) {
                unsigned short h0, l0, h1, l1;
                bsplit(hv[2 * r], h0, l0); bsplit(hv[2 * r + 1], h1, l1);
                int kp = (ad8 >> 1) + r;
                su[Hh_ + row * 36 + kp] = pk16(h0, h1);
                su[Hl_ + row * 36 + kp] = pk16(l0, l1);
            }
            // prefetch next iteration's coords (hidden across this iteration)
            int pn = p + gridDim.x;
            if (pn < B_ * S_ / 2) {
                const float* gpn = g_groups + ((size_t)(2 * pn + agrp)) * 96;
                ngc0 = __ldg(gpn + lane);
                ngc1 = __ldg(gpn + 32 + lane);
                ngc2 = __ldg(gpn + 64 + lane);
            }
        }
        __syncthreads();

        // ---- B: u = P h ; v = Wv h + bv ----
        {
            int n0 = nt * 8 + qg;
            float uh[2][4] = {}, ue[2][4] = {}, vh[2][4] = {}, ve[2][4] = {};
#pragma unroll
            for (int kt = 0; kt < 4; ++kt) {
                int kp0 = kt * 8 + t4, kp1 = kp0 + 4;
                unsigned pbh0 = su[PBh_ + kp0 * 72 + n0];
                unsigned pbh1 = su[PBh_ + kp1 * 72 + n0];
                unsigned pbl0 = su[PBl_ + kp0 * 72 + n0];
                unsigned pbl1 = su[PBl_ + kp1 * 72 + n0];
                unsigned wvh0 = su[WVh_ + kp0 * 72 + n0];
                unsigned wvh1 = su[WVh_ + kp1 * 72 + n0];
                unsigned wvl0 = su[WVl_ + kp0 * 72 + n0];
                unsigned wvl1 = su[WVl_ + kp1 * 72 + n0];
#pragma unroll
                for (int t = 0; t < 2; ++t) {
                    int ra0 = mt0 * 16 + t * 32 + qg, ra1 = ra0 + 8;
                    unsigned ah[4], al[4];
                    ah[0] = su[Hh_ + ra0 * 36 + kp0];
                    ah[1] = su[Hh_ + ra1 * 36 + kp0];
                    ah[2] = su[Hh_ + ra0 * 36 + kp1];
                    ah[3] = su[Hh_ + ra1 * 36 + kp1];
                    al[0] = su[Hl_ + ra0 * 36 + kp0];
                    al[1] = su[Hl_ + ra1 * 36 + kp0];
                    al[2] = su[Hl_ + ra0 * 36 + kp1];
                    al[3] = su[Hl_ + ra1 * 36 + kp1];
                    mma16(uh[t], ah, pbh0, pbh1);
                    mma16(ue[t], ah, pbl0, pbl1);
                    mma16(ue[t], al, pbh0, pbh1);
                    mma16(vh[t], ah, wvh0, wvh1);
                    mma16(ve[t], ah, wvl0, wvl1);
                    mma16(ve[t], al, wvh0, wvh1);
                }
            }
            int cc0 = nt * 8 + 2 * t4, cc1 = cc0 + 1;
            float bv0 = sm[BV_ + cc0], bv1 = sm[BV_ + cc1];
            int kpU = nt * 4 + t4;
#pragma unroll
            for (int t = 0; t < 2; ++t) {
                int ra0 = mt0 * 16 + t * 32 + qg, ra1 = ra0 + 8;
                float u0 = uh[t][0] + ue[t][0], u1 = uh[t][1] + ue[t][1];
                float u2 = uh[t][2] + ue[t][2], u3 = uh[t][3] + ue[t][3];
                float v0 = vh[t][0] + ve[t][0] + bv0, v1 = vh[t][1] + ve[t][1] + bv1;
                float v2 = vh[t][2] + ve[t][2] + bv0, v3 = vh[t][3] + ve[t][3] + bv1;
                unsigned short h0, l0, h1, l1;
                bsplit(u0, h0, l0); bsplit(u1, h1, l1);
                su[Uh_ + kpU * 72 + ra0] = pk16(h0, h1);
                su[Ul_ + kpU * 72 + ra0] = pk16(l0, l1);
                bsplit(u2, h0, l0); bsplit(u3, h1, l1);
                su[Uh_ + kpU * 72 + ra1] = pk16(h0, h1);
                su[Ul_ + kpU * 72 + ra1] = pk16(l0, l1);
                unsigned s0 = bsplitw(v0), s1 = bsplitw(v1);
                unsigned s2 = bsplitw(v2), s3 = bsplitw(v3);
                unsigned p0 = __shfl_xor_sync(FULLMASK, s0, 4);
                unsigned p1 = __shfl_xor_sync(FULLMASK, s1, 4);
                unsigned p2 = __shfl_xor_sync(FULLMASK, s2, 4);
                unsigned p3 = __shfl_xor_sync(FULLMASK, s3, 4);
                if ((qg & 1) == 0) {
                    int kv0 = t * 16 + mt0 * 8 + (qg >> 1);
                    int kv1 = kv0 + 4;
                    su[Vh_ + kv0 * 72 + cc0] = __byte_perm(s0, p0, 0x5410);
                    su[Vl_ + kv0 * 72 + cc0] = __byte_perm(s0, p0, 0x7632);
                    su[Vh_ + kv0 * 72 + cc1] = __byte_perm(s1, p1, 0x5410);
                    su[Vl_ + kv0 * 72 + cc1] = __byte_perm(s1, p1, 0x7632);
                    su[Vh_ + kv1 * 72 + cc0] = __byte_perm(s2, p2, 0x5410);
                    su[Vl_ + kv1 * 72 + cc0] = __byte_perm(s2, p2, 0x7632);
                    su[Vh_ + kv1 * 72 + cc1] = __byte_perm(s3, p3, 0x5410);
                    su[Vl_ + kv1 * 72 + cc1] = __byte_perm(s3, p3, 0x7632);
                }
            }
        }
        if (warp < 2) {
            int grp = warp;
            unsigned long long rc = 0;
#pragma unroll 8
            for (int cc = 0; cc < 64; ++cc) {
                float hv = sm[H32_ + cc * 68 + grp * 32 + lane];
                rc = fma2_(*(const unsigned long long*)&sm[WQKB_ + 2 * cc],
                           pk2(hv, hv), rc);
            }
            float rB, cA;
            upk2(rc, rB, cA);
            sm[RBs_ + grp * 32 + lane] = rB;
            sm[CAs_ + grp * 32 + lane] = cA;
        }
        __syncthreads();

        // ---- C: logits = h^T u ----
        {
            int grp = warp >> 3, cmt = (warp >> 2) & 1, cnt = warp & 3;
            int ra0 = grp * 32 + cmt * 16 + qg, ra1 = ra0 + 8;
            int n0 = grp * 32 + cnt * 8 + qg;
            float ch[4] = {0, 0, 0, 0}, ce[4] = {0, 0, 0, 0};
#pragma unroll
            for (int kt = 0; kt < 4; ++kt) {
                int kp0 = kt * 8 + t4, kp1 = kp0 + 4;
                unsigned ah[4], al[4];
                ah[0] = su[Hh_ + ra0 * 36 + kp0];
                ah[1] = su[Hh_ + ra1 * 36 + kp0];
                ah[2] = su[Hh_ + ra0 * 36 + kp1];
                ah[3] = su[Hh_ + ra1 * 36 + kp1];
                al[0] = su[Hl_ + ra0 * 36 + kp0];
                al[1] = su[Hl_ + ra1 * 36 + kp0];
                al[2] = su[Hl_ + ra0 * 36 + kp1];
                al[3] = su[Hl_ + ra1 * 36 + kp1];
                unsigned bh0 = su[Uh_ + kp0 * 72 + n0];
                unsigned bh1 = su[Uh_ + kp1 * 72 + n0];
                unsigned bl0 = su[Ul_ + kp0 * 72 + n0];
                unsigned bl1 = su[Ul_ + kp1 * 72 + n0];
                mma16(ch, ah, bh0, bh1);
                mma16(ce, ah, bl0, bl1);
                mma16(ce, al, bh0, bh1);
            }
            int jc0 = cnt * 8 + 2 * t4;
            sm[LG_ + ra0 * 33 + jc0]     = ch[0] + ce[0];
            sm[LG_ + ra0 * 33 + jc0 + 1] = ch[1] + ce[1];
            sm[LG_ + ra1 * 33 + jc0]     = ch[2] + ce[2];
            sm[LG_ + ra1 * 33 + jc0 + 1] = ch[3] + ce[3];
        }
        __syncthreads();

        // ---- softmax ----
        {
            float cb = sm[CB_];
#pragma unroll
            for (int k = 0; k < 4; ++k) {
                int r = warp + 16 * k;
                int grp = r >> 5, i = r & 31;
                float a = (sm[LG_ + r * 33 + lane] + sm[CAs_ + grp * 32 + i] +
                           sm[RBs_ + grp * 32 + lane] + cb) * 0.125f;
                float m = a;
#pragma unroll
                for (int off = 16; off; off >>= 1)
                    m = fmaxf(m, __shfl_xor_sync(FULLMASK, m, off));
                float e = expf(a - m);
                float s = e;
#pragma unroll
                for (int off = 16; off; off >>= 1)
                    s += __shfl_xor_sync(FULLMASK, s, off);
                float pf = e / s;
                unsigned w0 = bsplitw(pf);
                unsigned q0 = __shfl_xor_sync(FULLMASK, w0, 1);
                if ((lane & 1) == 0) {
                    int jp = lane >> 1;
                    su[ATTh_ + r * 20 + jp] = __byte_perm(w0, q0, 0x5410);
                    su[ATTl_ + r * 20 + jp] = __byte_perm(w0, q0, 0x7632);
                }
            }
        }
        __syncthreads();

        // ---- D: res = attn v ; T = res + h ----
        float rr[8];
        {
            int n0 = nt * 8 + qg;
            int dc0 = nt * 8 + 2 * t4, dc1 = dc0 + 1;
            int kpT = nt * 4 + t4;
#pragma unroll
            for (int grp = 0; grp < 2; ++grp) {
                int ra0 = grp * 32 + mt0 * 16 + qg, ra1 = ra0 + 8;
                float rh[4] = {0, 0, 0, 0}, re[4] = {0, 0, 0, 0};
#pragma unroll
                for (int kt = 0; kt < 2; ++kt) {
                    int kp0 = kt * 8 + t4, kp1 = kp0 + 4;
                    unsigned ah[4], al[4];
                    ah[0] = su[ATTh_ + ra0 * 20 + kp0];
                    ah[1] = su[ATTh_ + ra1 * 20 + kp0];
                    ah[2] = su[ATTh_ + ra0 * 20 + kp1];
                    ah[3] = su[ATTh_ + ra1 * 20 + kp1];
                    al[0] = su[ATTl_ + ra0 * 20 + kp0];
                    al[1] = su[ATTl_ + ra1 * 20 + kp0];
                    al[2] = su[ATTl_ + ra0 * 20 + kp1];
                    al[3] = su[ATTl_ + ra1 * 20 + kp1];
                    int kg0 = grp * 16 + kp0, kg1 = grp * 16 + kp1;
                    unsigned bh0 = su[Vh_ + kg0 * 72 + n0];
                    unsigned bh1 = su[Vh_ + kg1 * 72 + n0];
                    unsigned bl0 = su[Vl_ + kg0 * 72 + n0];
                    unsigned bl1 = su[Vl_ + kg1 * 72 + n0];
                    mma16(rh, ah, bh0, bh1);
                    mma16(re, ah, bl0, bl1);
                    mma16(re, al, bh0, bh1);
                }
                float r0 = rh[0] + re[0], r1 = rh[1] + re[1];
                float r2 = rh[2] + re[2], r3 = rh[3] + re[3];
                rr[grp * 4 + 0] = r0; rr[grp * 4 + 1] = r1;
                rr[grp * 4 + 2] = r2; rr[grp * 4 + 3] = r3;
                float t0 = r0 + sm[H32_ + dc0 * 68 + ra0];
                float t1 = r1 + sm[H32_ + dc1 * 68 + ra0];
                float t2 = r2 + sm[H32_ + dc0 * 68 + ra1];
                float t3 = r3 + sm[H32_ + dc1 * 68 + ra1];
                unsigned short h0, l0, h1, l1;
                bsplit(t0, h0, l0); bsplit(t1, h1, l1);
                su[Th_ + ra0 * 36 + kpT] = pk16(h0, h1);
                su[Tl_ + ra0 * 36 + kpT] = pk16(l0, l1);
                bsplit(t2, h0, l0); bsplit(t3, h1, l1);
                su[Th_ + ra1 * 36 + kpT] = pk16(h0, h1);
                su[Tl_ + ra1 * 36 + kpT] = pk16(l0, l1);
            }
        }
        __syncthreads();

        // ---- E: G1 = gelu(Wg1 T + bg1) ----
        {
            int n0 = nt * 8 + qg;
            int dc0 = nt * 8 + 2 * t4, dc1 = dc0 + 1;
            float b0 = sm[BG1_ + dc0], b1 = sm[BG1_ + dc1];
            int kpT = nt * 4 + t4;
            float gh[2][4] = {}, ge[2][4] = {};
#pragma unroll
            for (int kt = 0; kt < 4; ++kt) {
                int kp0 = kt * 8 + t4, kp1 = kp0 + 4;
                unsigned bh0 = su[WG1h_ + kp0 * 72 + n0];
                unsigned bh1 = su[WG1h_ + kp1 * 72 + n0];
                unsigned bl0 = su[WG1l_ + kp0 * 72 + n0];
                unsigned bl1 = su[WG1l_ + kp1 * 72 + n0];
#pragma unroll
                for (int t = 0; t < 2; ++t) {
                    int ra0 = t * 32 + mt0 * 16 + qg, ra1 = ra0 + 8;
                    unsigned ah[4], al[4];
                    ah[0] = su[Th_ + ra0 * 36 + kp0];
                    ah[1] = su[Th_ + ra1 * 36 + kp0];
                    ah[2] = su[Th_ + ra0 * 36 + kp1];
                    ah[3] = su[Th_ + ra1 * 36 + kp1];
                    al[0] = su[Tl_ + ra0 * 36 + kp0];
                    al[1] = su[Tl_ + ra1 * 36 + kp0];
                    al[2] = su[Tl_ + ra0 * 36 + kp1];
                    al[3] = su[Tl_ + ra1 * 36 + kp1];
                    mma16(gh[t], ah, bh0, bh1);
                    mma16(ge[t], ah, bl0, bl1);
                    mma16(ge[t], al, bh0, bh1);
                }
            }
#pragma unroll
            for (int t = 0; t < 2; ++t) {
                int ra0 = t * 32 + mt0 * 16 + qg, ra1 = ra0 + 8;
                float g0 = gelu_exact(gh[t][0] + ge[t][0] + b0);
                float g1 = gelu_exact(gh[t][1] + ge[t][1] + b1);
                float g2 = gelu_exact(gh[t][2] + ge[t][2] + b0);
                float g3 = gelu_exact(gh[t][3] + ge[t][3] + b1);
                unsigned short h0, l0, h1, l1;
                bsplit(g0, h0, l0); bsplit(g1, h1, l1);
                su[G1h_ + ra0 * 36 + kpT] = pk16(h0, h1);
                su[G1l_ + ra0 * 36 + kpT] = pk16(l0, l1);
                bsplit(g2, h0, l0); bsplit(g3, h1, l1);
                su[G1h_ + ra1 * 36 + kpT] = pk16(h0, h1);
                su[G1l_ + ra1 * 36 + kpT] = pk16(l0, l1);
            }
        }
        __syncthreads();

        // ---- F: out = Wg2 G1 + bg2 + res ; maxpool ----
        {
            int n0 = nt * 8 + qg;
            int dc0 = nt * 8 + 2 * t4, dc1 = dc0 + 1;
            float b0 = sm[BG2_ + dc0], b1 = sm[BG2_ + dc1];
            float fh[2][4] = {}, fe[2][4] = {};
#pragma unroll
            for (int kt = 0; kt < 4; ++kt) {
                int kp0 = kt * 8 + t4, kp1 = kp0 + 4;
                unsigned bh0 = su[WG2h_ + kp0 * 72 + n0];
                unsigned bh1 = su[WG2h_ + kp1 * 72 + n0];
                unsigned bl0 = su[WG2l_ + kp0 * 72 + n0];
                unsigned bl1 = su[WG2l_ + kp1 * 72 + n0];
#pragma unroll
                for (int t = 0; t < 2; ++t) {
                    int ra0 = t * 32 + mt0 * 16 + qg, ra1 = ra0 + 8;
                    unsigned ah[4], al[4];
                    ah[0] = su[G1h_ + ra0 * 36 + kp0];
                    ah[1] = su[G1h_ + ra1 * 36 + kp0];
                    ah[2] = su[G1h_ + ra0 * 36 + kp1];
                    ah[3] = su[G1h_ + ra1 * 36 + kp1];
                    al[0] = su[G1l_ + ra0 * 36 + kp0];
                    al[1] = su[G1l_ + ra1 * 36 + kp0];
                    al[2] = su[G1l_ + ra0 * 36 + kp1];
                    al[3] = su[G1l_ + ra1 * 36 + kp1];
                    mma16(fh[t], ah, bh0, bh1);
                    mma16(fe[t], ah, bl0, bl1);
                    mma16(fe[t], al, bh0, bh1);
                }
            }
#pragma unroll
            for (int t = 0; t < 2; ++t) {
                float v0 = fh[t][0] + fe[t][0] + b0 + rr[t * 4 + 0];
                float v1 = fh[t][1] + fe[t][1] + b1 + rr[t * 4 + 1];
                float v2 = fh[t][2] + fe[t][2] + b0 + rr[t * 4 + 2];
                float v3 = fh[t][3] + fe[t][3] + b1 + rr[t * 4 + 3];
                float m0 = fmaxf(v0, v2), m1 = fmaxf(v1, v3);
#pragma unroll
                for (int off = 4; off < 32; off <<= 1) {
                    m0 = fmaxf(m0, __shfl_xor_sync(FULLMASK, m0, off));
                    m1 = fmaxf(m1, __shfl_xor_sync(FULLMASK, m1, off));
                }
                if (lane < 4) {
                    sm[MP_ + t * 128 + mt0 * 64 + nt * 8 + 2 * t4]     = m0;
                    sm[MP_ + t * 128 + mt0 * 64 + nt * 8 + 2 * t4 + 1] = m1;
                }
            }
        }
        __syncthreads();
        if (tid < 128) {
            int grp = tid >> 6, d = tid & 63;
            out[(size_t)(2 * p + grp) * 67 + 3 + d] =
                fmaxf(sm[MP_ + grp * 128 + d], sm[MP_ + grp * 128 + 64 + d]);
        }
        __syncthreads();
    }
}

// ============================ launch ======================================
extern "C" void kernel_launch(void* const* d_in, const int* in_sizes, int n_in,
                              void* d_out, int out_size) {
    (void)in_sizes; (void)n_in; (void)out_size;
    const float* x        = (const float*)d_in[0];
    const float* w_alpha  = (const float*)d_in[1];
    const float* b_alpha  = (const float*)d_in[2];
    const float* bn_gamma = (const float*)d_in[3];
    const float* bn_beta  = (const float*)d_in[4];
    const float* bn_mean  = (const float*)d_in[5];
    const float* bn_var   = (const float*)d_in[6];
    const float* w_q      = (const float*)d_in[7];
    const float* b_q      = (const float*)d_in[8];
    const float* w_k      = (const float*)d_in[9];
    const float* b_k      = (const float*)d_in[10];
    const float* w_v      = (const float*)d_in[11];
    const float* b_v      = (const float*)d_in[12];
    const float* w_g1     = (const float*)d_in[13];
    const float* b_g1     = (const float*)d_in[14];
    const float* w_g2     = (const float*)d_in[15];
    const float* b_g2     = (const float*)d_in[16];
    float* out = (float*)d_out;

    cudaFuncSetAttribute(fps_kernel,
                         cudaFuncAttributeMaxDynamicSharedMemorySize, 49664);
    cudaFuncSetAttribute(knn_kernel,
                         cudaFuncAttributeMaxDynamicSharedMemorySize, 65536);
    cudaFuncSetAttribute(group_kernel,
                         cudaFuncAttributeMaxDynamicSharedMemorySize, SMTOT * 4);

    fps_kernel<<<B_, 512, 49664>>>(x, out);
    knn_kernel<<<B_ * 4, 1024, 65536>>>(x);
    group_kernel<<<148, 512, SMTOT * 4>>>(w_alpha, b_alpha, bn_gamma, bn_beta,
                                          bn_mean, bn_var, w_q, b_q, w_k, b_k,
                                          w_v, b_v, w_g1, b_g1, w_g2, b_g2, out);
}

// round 17
// speedup vs baseline: 3.5214x; 1.0071x over previous
#include <cuda_runtime.h>
#include <math.h>

#define B_   32
#define N_   4096
#define S_   512
#define FULLMASK 0xffffffffu

__device__ float g_centroid[B_ * S_ * 3];
__device__ float g_groups[B_ * S_ * 96];   // [bs][c][k]

// ---------------- helpers -------------------------------------------------
__device__ __forceinline__ unsigned long long pk2(float lo, float hi) {
    unsigned long long r;
    asm("mov.b64 %0, {%1, %2};" : "=l"(r) : "f"(lo), "f"(hi));
    return r;
}
__device__ __forceinline__ void upk2(unsigned long long v, float& lo, float& hi) {
    asm("mov.b64 {%0, %1}, %2;" : "=f"(lo), "=f"(hi) : "l"(v));
}
__device__ __forceinline__ unsigned long long fma2_(unsigned long long a,
                                                   unsigned long long b,
                                                   unsigned long long c) {
    unsigned long long d;
    asm("fma.rn.f32x2 %0, %1, %2, %3;" : "=l"(d) : "l"(a), "l"(b), "l"(c));
    return d;
}
__device__ __forceinline__ unsigned short bh16(float x) {
    unsigned short r;
    asm("cvt.rn.bf16.f32 %0, %1;" : "=h"(r) : "f"(x));
    return r;
}
__device__ __forceinline__ float bf2f(unsigned short h) {
    return __uint_as_float((unsigned)h << 16);
}
__device__ __forceinline__ void bsplit(float x, unsigned short& h, unsigned short& l) {
    h = bh16(x);
    l = bh16(x - bf2f(h));
}
__device__ __forceinline__ unsigned pk16(unsigned short a, unsigned short b) {
    return (unsigned)a | ((unsigned)b << 16);
}
__device__ __forceinline__ unsigned bsplitw(float x) {
    unsigned short h, l;
    bsplit(x, h, l);
    return pk16(h, l);
}
__device__ __forceinline__ unsigned ford(float x) {
    unsigned b = __float_as_uint(x);
    return b ^ (((int)b >> 31) | 0x80000000u);
}
__device__ __forceinline__ void mma16(float* c, const unsigned* a,
                                      unsigned b0, unsigned b1) {
    asm("mma.sync.aligned.m16n8k16.row.col.f32.bf16.bf16.f32 "
        "{%0,%1,%2,%3},{%4,%5,%6,%7},{%8,%9},{%0,%1,%2,%3};"
        : "+f"(c[0]), "+f"(c[1]), "+f"(c[2]), "+f"(c[3])
        : "r"(a[0]), "r"(a[1]), "r"(a[2]), "r"(a[3]), "r"(b0), "r"(b1));
}
__device__ __forceinline__ float gelu_exact(float v) {
    return 0.5f * v * (1.0f + erff(v * 0.70710678118654752440f));
}

// ============================ FPS (512 thr, 8 pts/thr) ====================
__global__ __launch_bounds__(512) void fps_kernel(const float* __restrict__ x,
                                                  float* __restrict__ out) {
    extern __shared__ float smf[];
    float* sx0 = smf;
    float* sx1 = smf + 4096;
    float* sx2 = smf + 8192;
    unsigned long long* pb = (unsigned long long*)(smf + 12288);

    int b = blockIdx.x, tid = threadIdx.x;
    int lane = tid & 31, warp = tid >> 5;
    const float* xb = x + (size_t)b * N_ * 3;

    float px[8], py[8], pz[8], dist[8];
#pragma unroll
    for (int i = 0; i < 8; ++i) {
        int n = tid + i * 512;
        float a0 = xb[n * 3 + 0], a1 = xb[n * 3 + 1], a2 = xb[n * 3 + 2];
        px[i] = a0; py[i] = a1; pz[i] = a2;
        sx0[n] = a0; sx1[n] = a1; sx2[n] = a2;
        dist[i] = 1e10f;
    }
    __syncthreads();

    int last = 0;
    for (int s = 0; s < S_; ++s) {
        float c0 = sx0[last], c1 = sx1[last], c2 = sx2[last];
        if (tid == 0) {
            int bs = b * S_ + s;
            out[(size_t)bs * 67 + 0] = c0;
            out[(size_t)bs * 67 + 1] = c1;
            out[(size_t)bs * 67 + 2] = c2;
            g_centroid[bs * 3 + 0] = c0;
            g_centroid[bs * 3 + 1] = c1;
            g_centroid[bs * 3 + 2] = c2;
        }
        float bv = -1.0f;
        unsigned bi = 0;
#pragma unroll
        for (int i = 0; i < 8; ++i) {
            float dx = px[i] - c0, dy = py[i] - c1, dz = pz[i] - c2;
            float d = (dx * dx + dy * dy) + dz * dz;
            float nd = fminf(dist[i], d);
            dist[i] = nd;
            if (nd > bv) { bv = nd; bi = (unsigned)(tid + i * 512); }
        }
        unsigned vb = __float_as_uint(bv);
        unsigned wmax = __reduce_max_sync(FULLMASK, vb);
        unsigned cand = (vb == wmax) ? bi : 0xffffffffu;
        unsigned widx = __reduce_min_sync(FULLMASK, cand);
        int par = s & 1;
        if (lane == 0)
            pb[par * 16 + warp] =
                ((unsigned long long)wmax << 32) |
                (unsigned long long)(0xffffffffu - widx);
        __syncthreads();
        unsigned long long k = pb[par * 16 + (lane & 15)];
        unsigned kv = (unsigned)(k >> 32);
        unsigned bmax = __reduce_max_sync(FULLMASK, kv);
        unsigned enc = (kv == bmax) ? (unsigned)k : 0u;
        unsigned benc = __reduce_max_sync(FULLMASK, enc);
        last = (int)(0xffffffffu - benc);
    }
}

// ===== KNN v5: unsorted top-32 + REDUX max-key, 64-pt tiles, 1024 thr =====
__global__ __launch_bounds__(1024) void knn_kernel(const float* __restrict__ x) {
    int b    = blockIdx.x >> 2;
    int part = blockIdx.x & 3;
    extern __shared__ float smk[];
    float* sx0 = smk;
    float* sx1 = smk + 4096;
    float* sx2 = smk + 8192;
    float* sxs = smk + 12288;

    const float* xb = x + (size_t)b * N_ * 3;
    for (int i = threadIdx.x; i < N_; i += 1024) {
        float a0 = xb[i * 3 + 0], a1 = xb[i * 3 + 1], a2 = xb[i * 3 + 2];
        sx0[i] = a0; sx1[i] = a1; sx2[i] = a2;
        sxs[i] = (a0 * a0 + a1 * a1) + a2 * a2;
    }
    __syncthreads();

    int warp = threadIdx.x >> 5, lane = threadIdx.x & 31;
    for (int jj = 0; jj < 4; ++jj) {
        int s  = part * 128 + jj * 32 + warp;
        int bs = b * S_ + s;
        float c0 = g_centroid[bs * 3 + 0];
        float c1 = g_centroid[bs * 3 + 1];
        float c2 = g_centroid[bs * 3 + 2];
        float cs = (c0 * c0 + c1 * c1) + c2 * c2;

        unsigned lb, li, mb, mi;
        {
            int n = lane;
            float dot = (c0 * sx0[n] + c1 * sx1[n]) + c2 * sx2[n];
            float d2  = (cs + sxs[n]) - 2.0f * dot;
            lb = ford(d2);
            li = (unsigned)n;
            mb = __reduce_max_sync(FULLMASK, lb);
            mi = __reduce_max_sync(FULLMASK, (lb == mb) ? li : 0u);
        }
        {
            int n = 32 + lane;
            float dot = (c0 * sx0[n] + c1 * sx1[n]) + c2 * sx2[n];
            float d2  = (cs + sxs[n]) - 2.0f * dot;
            unsigned db = ford(d2);
            bool cand = (db < mb) || (db == mb && (unsigned)n < mi);
            unsigned m = __ballot_sync(FULLMASK, cand);
            while (m) {
                int src = __ffs(m) - 1;
                m &= m - 1;
                unsigned cdb = __shfl_sync(FULLMASK, db, src);
                unsigned cn  = (unsigned)(32 + src);
                if (cdb < mb || (cdb == mb && cn < mi)) {
                    if (lb == mb && li == mi) { lb = cdb; li = cn; }
                    mb = __reduce_max_sync(FULLMASK, lb);
                    mi = __reduce_max_sync(FULLMASK, (lb == mb) ? li : 0u);
                }
            }
        }
        for (int base = 64; base < N_; base += 64) {
            int n1 = base + lane, n2 = n1 + 32;
            float dot1 = (c0 * sx0[n1] + c1 * sx1[n1]) + c2 * sx2[n1];
            float d21  = (cs + sxs[n1]) - 2.0f * dot1;
            float dot2 = (c0 * sx0[n2] + c1 * sx1[n2]) + c2 * sx2[n2];
            float d22  = (cs + sxs[n2]) - 2.0f * dot2;
            unsigned db1 = ford(d21), db2 = ford(d22);
            bool c1f = (db1 < mb) || (db1 == mb && (unsigned)n1 < mi);
            bool c2f = (db2 < mb) || (db2 == mb && (unsigned)n2 < mi);
            unsigned m1 = __ballot_sync(FULLMASK, c1f);
            unsigned m2 = __ballot_sync(FULLMASK, c2f);
            while (m1) {
                int src = __ffs(m1) - 1;
                m1 &= m1 - 1;
                unsigned cdb = __shfl_sync(FULLMASK, db1, src);
                unsigned cn  = (unsigned)(base + src);
                if (cdb < mb || (cdb == mb && cn < mi)) {
                    if (lb == mb && li == mi) { lb = cdb; li = cn; }
                    mb = __reduce_max_sync(FULLMASK, lb);
                    mi = __reduce_max_sync(FULLMASK, (lb == mb) ? li : 0u);
                }
            }
            while (m2) {
                int src = __ffs(m2) - 1;
                m2 &= m2 - 1;
                unsigned cdb = __shfl_sync(FULLMASK, db2, src);
                unsigned cn  = (unsigned)(base + 32 + src);
                if (cdb < mb || (cdb == mb && cn < mi)) {
                    if (lb == mb && li == mi) { lb = cdb; li = cn; }
                    mb = __reduce_max_sync(FULLMASK, lb);
                    mi = __reduce_max_sync(FULLMASK, (lb == mb) ? li : 0u);
                }
            }
        }
        float* gp = g_groups + (size_t)bs * 96;
        int idx = (int)li;
        gp[lane]      = sx0[idx] - c0;
        gp[32 + lane] = sx1[idx] - c1;
        gp[64 + lane] = sx2[idx] - c2;
    }
}

// ================= per-group compute: 2 groups / iteration ================
#define PBh_   0
#define PBl_   2304
#define WVh_   4608
#define WVl_   6912
#define WG1h_  9216
#define WG1l_  11520
#define WG2h_  13824
#define WG2l_  16128
#define WA_    18432
#define WQKB_  18624
#define BV_    18752
#define BG1_   18816
#define BG2_   18880
#define BA_    18944
#define BNM_   19008
#define BNR_   19072
#define BNG_   19136
#define BNB_   19200
#define CB_    19264
#define H32_   19272
#define Hh_    23624
#define Hl_    25928
#define Uh_    28232
#define Ul_    30536
#define Vh_    32840
#define Vl_    35144
#define ATTh_  37448
#define ATTl_  38728
#define Th_    40008
#define Tl_    42312
#define G1h_   44616
#define G1l_   46920
#define LG_    49224
#define RBs_   51336
#define CAs_   51400
#define MP_    51464
#define SMTOT  51720
#define SCRQ_  19272
#define SCRK_  23368
#define SCRP_  27464

__global__ __launch_bounds__(512) void group_kernel(
    const float* __restrict__ w_alpha, const float* __restrict__ b_alpha,
    const float* __restrict__ bn_gamma, const float* __restrict__ bn_beta,
    const float* __restrict__ bn_mean,  const float* __restrict__ bn_var,
    const float* __restrict__ w_q, const float* __restrict__ b_q,
    const float* __restrict__ w_k, const float* __restrict__ b_k,
    const float* __restrict__ w_v, const float* __restrict__ b_v,
    const float* __restrict__ w_g1, const float* __restrict__ b_g1,
    const float* __restrict__ w_g2, const float* __restrict__ b_g2,
    float* __restrict__ out) {
    extern __shared__ float sm[];
    unsigned* su = (unsigned*)sm;
    int tid = threadIdx.x;
    int warp = tid >> 5, lane = tid & 31;
    int qg = lane >> 2, t4 = lane & 3;

    // ---- init phase 1 ----
    for (int i = tid; i < 4096; i += 512) {
        sm[SCRQ_ + i] = w_q[i];
        sm[SCRK_ + i] = w_k[i];
    }
    for (int i = tid; i < 2048; i += 512) {
        int d = i >> 5, cp = i & 31;
        int i0 = d * 64 + 2 * cp;
        unsigned short h0, l0, h1, l1;
        bsplit(w_v[i0], h0, l0); bsplit(w_v[i0 + 1], h1, l1);
        su[WVh_ + cp * 72 + d] = pk16(h0, h1);
        su[WVl_ + cp * 72 + d] = pk16(l0, l1);
        bsplit(w_g1[i0], h0, l0); bsplit(w_g1[i0 + 1], h1, l1);
        su[WG1h_ + cp * 72 + d] = pk16(h0, h1);
        su[WG1l_ + cp * 72 + d] = pk16(l0, l1);
        bsplit(w_g2[i0], h0, l0); bsplit(w_g2[i0 + 1], h1, l1);
        su[WG2h_ + cp * 72 + d] = pk16(h0, h1);
        su[WG2l_ + cp * 72 + d] = pk16(l0, l1);
    }
    if (tid < 64) {
        sm[BV_ + tid] = b_v[tid];
        sm[BG1_ + tid] = b_g1[tid]; sm[BG2_ + tid] = b_g2[tid];
        sm[BA_ + tid] = b_alpha[tid];
        sm[BNM_ + tid] = bn_mean[tid];
        sm[BNR_ + tid] = rsqrtf(bn_var[tid] + 1e-5f);
        sm[BNG_ + tid] = bn_gamma[tid];
        sm[BNB_ + tid] = bn_beta[tid];
    }
    __syncthreads();

    // ---- init phase 2 ----
    for (int i = tid; i < 4096; i += 512) {
        int c = i & 63, cc = i >> 6;
        float s = 0.f;
#pragma unroll 8
        for (int d = 0; d < 64; ++d)
            s += sm[SCRQ_ + d * 64 + c] * sm[SCRK_ + d * 64 + cc];
        sm[SCRP_ + cc * 64 + c] = s;
    }
    if (tid < 192) {
        int d = tid / 3, c = tid % 3;
        float sc = sm[BNR_ + d] * sm[BNG_ + d];
        sm[WA_ + c * 64 + d] = w_alpha[tid] * sc;
    }
    if (tid >= 192 && tid < 256) {
        int d = tid - 192;
        float sc = sm[BNR_ + d] * sm[BNG_ + d];
        float sh = sm[BNB_ + d] - sm[BNM_ + d] * sc;
        sm[BA_ + d] = sm[BA_ + d] * sc + sh;
    }
    if (tid >= 256 && tid < 320) {
        int c = tid - 256;
        float aq = 0.f, ak = 0.f;
#pragma unroll 8
        for (int d = 0; d < 64; ++d) {
            aq += sm[SCRQ_ + d * 64 + c] * b_k[d];
            ak += sm[SCRK_ + d * 64 + c] * b_q[d];
        }
        sm[WQKB_ + 2 * c]     = ak;
        sm[WQKB_ + 2 * c + 1] = aq;
    }
    if (tid == 511) {
        float s = 0.f;
        for (int d = 0; d < 64; ++d) s += b_q[d] * b_k[d];
        sm[CB_] = s;
    }
    __syncthreads();

    // ---- init phase 3 ----
    for (int i = tid; i < 2048; i += 512) {
        int ccp = i >> 6, c = i & 63;
        unsigned short h0, l0, h1, l1;
        bsplit(sm[SCRP_ + (2 * ccp) * 64 + c], h0, l0);
        bsplit(sm[SCRP_ + (2 * ccp + 1) * 64 + c], h1, l1);
        su[PBh_ + ccp * 72 + c] = pk16(h0, h1);
        su[PBl_ + ccp * 72 + c] = pk16(l0, l1);
    }
    __syncthreads();

    int mt0 = warp >> 3, nt = warp & 7;
    int agrp = warp & 1, ad8 = (warp >> 1) * 8;

    // prefetch first iteration's group coords
    float ngc0 = 0.f, ngc1 = 0.f, ngc2 = 0.f;
    {
        int p0 = blockIdx.x;
        if (p0 < B_ * S_ / 2) {
            const float* gp = g_groups + ((size_t)(2 * p0 + agrp)) * 96;
            ngc0 = __ldg(gp + lane);
            ngc1 = __ldg(gp + 32 + lane);
            ngc2 = __ldg(gp + 64 + lane);
        }
    }

    for (int p = blockIdx.x; p < B_ * S_ / 2; p += gridDim.x) {
        // ---- A ----
        {
            float gc0 = ngc0, gc1 = ngc1, gc2 = ngc2;
            int row = agrp * 32 + lane;
            float hv[8];
#pragma unroll
            for (int r = 0; r < 8; ++r) {
                int d = ad8 + r;
                float v = sm[WA_ + d] * gc0 + sm[WA_ + 64 + d] * gc1 +
                          sm[WA_ + 128 + d] * gc2 + sm[BA_ + d];
                v = gelu_exact(v);
                hv[r] = v;
                sm[H32_ + d * 68 + row] = v;
            }
#pragma unroll
            for (int r = 0; r < 4; ++r) {
                unsigned short h0, l0, h1, l1;
                bsplit(hv[2 * r], h0, l0); bsplit(hv[2 * r + 1], h1, l1);
                int kp = (ad8 >> 1) + r;
                su[Hh_ + row * 36 + kp] = pk16(h0, h1);
                su[Hl_ + row * 36 + kp] = pk16(l0, l1);
            }
            // prefetch next iteration's coords (hidden across this iteration)
            int pn = p + gridDim.x;
            if (pn < B_ * S_ / 2) {
                const float* gpn = g_groups + ((size_t)(2 * pn + agrp)) * 96;
                ngc0 = __ldg(gpn + lane);
                ngc1 = __ldg(gpn + 32 + lane);
                ngc2 = __ldg(gpn + 64 + lane);
            }
        }
        __syncthreads();

        // ---- B: u = P h ; v = Wv h + bv ----
        {
            int n0 = nt * 8 + qg;
            float uh[2][4] = {}, ue[2][4] = {}, vh[2][4] = {}, ve[2][4] = {};
#pragma unroll
            for (int kt = 0; kt < 4; ++kt) {
                int kp0 = kt * 8 + t4, kp1 = kp0 + 4;
                unsigned pbh0 = su[PBh_ + kp0 * 72 + n0];
                unsigned pbh1 = su[PBh_ + kp1 * 72 + n0];
                unsigned pbl0 = su[PBl_ + kp0 * 72 + n0];
                unsigned pbl1 = su[PBl_ + kp1 * 72 + n0];
                unsigned wvh0 = su[WVh_ + kp0 * 72 + n0];
                unsigned wvh1 = su[WVh_ + kp1 * 72 + n0];
                unsigned wvl0 = su[WVl_ + kp0 * 72 + n0];
                unsigned wvl1 = su[WVl_ + kp1 * 72 + n0];
#pragma unroll
                for (int t = 0; t < 2; ++t) {
                    int ra0 = mt0 * 16 + t * 32 + qg, ra1 = ra0 + 8;
                    unsigned ah[4], al[4];
                    ah[0] = su[Hh_ + ra0 * 36 + kp0];
                    ah[1] = su[Hh_ + ra1 * 36 + kp0];
                    ah[2] = su[Hh_ + ra0 * 36 + kp1];
                    ah[3] = su[Hh_ + ra1 * 36 + kp1];
                    al[0] = su[Hl_ + ra0 * 36 + kp0];
                    al[1] = su[Hl_ + ra1 * 36 + kp0];
                    al[2] = su[Hl_ + ra0 * 36 + kp1];
                    al[3] = su[Hl_ + ra1 * 36 + kp1];
                    mma16(uh[t], ah, pbh0, pbh1);
                    mma16(ue[t], ah, pbl0, pbl1);
                    mma16(ue[t], al, pbh0, pbh1);
                    mma16(vh[t], ah, wvh0, wvh1);
                    mma16(ve[t], ah, wvl0, wvl1);
                    mma16(ve[t], al, wvh0, wvh1);
                }
            }
            int cc0 = nt * 8 + 2 * t4, cc1 = cc0 + 1;
            float bv0 = sm[BV_ + cc0], bv1 = sm[BV_ + cc1];
            int kpU = nt * 4 + t4;
#pragma unroll
            for (int t = 0; t < 2; ++t) {
                int ra0 = mt0 * 16 + t * 32 + qg, ra1 = ra0 + 8;
                float u0 = uh[t][0] + ue[t][0], u1 = uh[t][1] + ue[t][1];
                float u2 = uh[t][2] + ue[t][2], u3 = uh[t][3] + ue[t][3];
                float v0 = vh[t][0] + ve[t][0] + bv0, v1 = vh[t][1] + ve[t][1] + bv1;
                float v2 = vh[t][2] + ve[t][2] + bv0, v3 = vh[t][3] + ve[t][3] + bv1;
                unsigned short h0, l0, h1, l1;
                bsplit(u0, h0, l0); bsplit(u1, h1, l1);
                su[Uh_ + kpU * 72 + ra0] = pk16(h0, h1);
                su[Ul_ + kpU * 72 + ra0] = pk16(l0, l1);
                bsplit(u2, h0, l0); bsplit(u3, h1, l1);
                su[Uh_ + kpU * 72 + ra1] = pk16(h0, h1);
                su[Ul_ + kpU * 72 + ra1] = pk16(l0, l1);
                unsigned s0 = bsplitw(v0), s1 = bsplitw(v1);
                unsigned s2 = bsplitw(v2), s3 = bsplitw(v3);
                unsigned p0 = __shfl_xor_sync(FULLMASK, s0, 4);
                unsigned p1 = __shfl_xor_sync(FULLMASK, s1, 4);
                unsigned p2 = __shfl_xor_sync(FULLMASK, s2, 4);
                unsigned p3 = __shfl_xor_sync(FULLMASK, s3, 4);
                if ((qg & 1) == 0) {
                    int kv0 = t * 16 + mt0 * 8 + (qg >> 1);
                    int kv1 = kv0 + 4;
                    su[Vh_ + kv0 * 72 + cc0] = __byte_perm(s0, p0, 0x5410);
                    su[Vl_ + kv0 * 72 + cc0] = __byte_perm(s0, p0, 0x7632);
                    su[Vh_ + kv0 * 72 + cc1] = __byte_perm(s1, p1, 0x5410);
                    su[Vl_ + kv0 * 72 + cc1] = __byte_perm(s1, p1, 0x7632);
                    su[Vh_ + kv1 * 72 + cc0] = __byte_perm(s2, p2, 0x5410);
                    su[Vl_ + kv1 * 72 + cc0] = __byte_perm(s2, p2, 0x7632);
                    su[Vh_ + kv1 * 72 + cc1] = __byte_perm(s3, p3, 0x5410);
                    su[Vl_ + kv1 * 72 + cc1] = __byte_perm(s3, p3, 0x7632);
                }
            }
        }
        if (warp < 2) {
            int grp = warp;
            unsigned long long rc = 0;
#pragma unroll 8
            for (int cc = 0; cc < 64; ++cc) {
                float hv = sm[H32_ + cc * 68 + grp * 32 + lane];
                rc = fma2_(*(const unsigned long long*)&sm[WQKB_ + 2 * cc],
                           pk2(hv, hv), rc);
            }
            float rB, cA;
            upk2(rc, rB, cA);
            sm[RBs_ + grp * 32 + lane] = rB;
            sm[CAs_ + grp * 32 + lane] = cA;
        }
        __syncthreads();

        // ---- C: logits = h^T u ----
        {
            int grp = warp >> 3, cmt = (warp >> 2) & 1, cnt = warp & 3;
            int ra0 = grp * 32 + cmt * 16 + qg, ra1 = ra0 + 8;
            int n0 = grp * 32 + cnt * 8 + qg;
            float ch[4] = {0, 0, 0, 0}, ce[4] = {0, 0, 0, 0};
#pragma unroll
            for (int kt = 0; kt < 4; ++kt) {
                int kp0 = kt * 8 + t4, kp1 = kp0 + 4;
                unsigned ah[4], al[4];
                ah[0] = su[Hh_ + ra0 * 36 + kp0];
                ah[1] = su[Hh_ + ra1 * 36 + kp0];
                ah[2] = su[Hh_ + ra0 * 36 + kp1];
                ah[3] = su[Hh_ + ra1 * 36 + kp1];
                al[0] = su[Hl_ + ra0 * 36 + kp0];
                al[1] = su[Hl_ + ra1 * 36 + kp0];
                al[2] = su[Hl_ + ra0 * 36 + kp1];
                al[3] = su[Hl_ + ra1 * 36 + kp1];
                unsigned bh0 = su[Uh_ + kp0 * 72 + n0];
                unsigned bh1 = su[Uh_ + kp1 * 72 + n0];
                unsigned bl0 = su[Ul_ + kp0 * 72 + n0];
                unsigned bl1 = su[Ul_ + kp1 * 72 + n0];
                mma16(ch, ah, bh0, bh1);
                mma16(ce, ah, bl0, bl1);
                mma16(ce, al, bh0, bh1);
            }
            int jc0 = cnt * 8 + 2 * t4;
            sm[LG_ + ra0 * 33 + jc0]     = ch[0] + ce[0];
            sm[LG_ + ra0 * 33 + jc0 + 1] = ch[1] + ce[1];
            sm[LG_ + ra1 * 33 + jc0]     = ch[2] + ce[2];
            sm[LG_ + ra1 * 33 + jc0 + 1] = ch[3] + ce[3];
        }
        __syncthreads();

        // ---- softmax ----
        {
            float cb = sm[CB_];
#pragma unroll
            for (int k = 0; k < 4; ++k) {
                int r = warp + 16 * k;
                int grp = r >> 5, i = r & 31;
                float a = (sm[LG_ + r * 33 + lane] + sm[CAs_ + grp * 32 + i] +
                           sm[RBs_ + grp * 32 + lane] + cb) * 0.125f;
                float m = a;
#pragma unroll
                for (int off = 16; off; off >>= 1)
                    m = fmaxf(m, __shfl_xor_sync(FULLMASK, m, off));
                float e = expf(a - m);
                float s = e;
#pragma unroll
                for (int off = 16; off; off >>= 1)
                    s += __shfl_xor_sync(FULLMASK, s, off);
                float pf = e / s;
                unsigned w0 = bsplitw(pf);
                unsigned q0 = __shfl_xor_sync(FULLMASK, w0, 1);
                if ((lane & 1) == 0) {
                    int jp = lane >> 1;
                    su[ATTh_ + r * 20 + jp] = __byte_perm(w0, q0, 0x5410);
                    su[ATTl_ + r * 20 + jp] = __byte_perm(w0, q0, 0x7632);
                }
            }
        }
        __syncthreads();

        // ---- D: res = attn v ; T = res + h ----
        float rr[8];
        {
            int n0 = nt * 8 + qg;
            int dc0 = nt * 8 + 2 * t4, dc1 = dc0 + 1;
            int kpT = nt * 4 + t4;
#pragma unroll
            for (int grp = 0; grp < 2; ++grp) {
                int ra0 = grp * 32 + mt0 * 16 + qg, ra1 = ra0 + 8;
                float rh[4] = {0, 0, 0, 0}, re[4] = {0, 0, 0, 0};
#pragma unroll
                for (int kt = 0; kt < 2; ++kt) {
                    int kp0 = kt * 8 + t4, kp1 = kp0 + 4;
                    unsigned ah[4], al[4];
                    ah[0] = su[ATTh_ + ra0 * 20 + kp0];
                    ah[1] = su[ATTh_ + ra1 * 20 + kp0];
                    ah[2] = su[ATTh_ + ra0 * 20 + kp1];
                    ah[3] = su[ATTh_ + ra1 * 20 + kp1];
                    al[0] = su[ATTl_ + ra0 * 20 + kp0];
                    al[1] = su[ATTl_ + ra1 * 20 + kp0];
                    al[2] = su[ATTl_ + ra0 * 20 + kp1];
                    al[3] = su[ATTl_ + ra1 * 20 + kp1];
                    int kg0 = grp * 16 + kp0, kg1 = grp * 16 + kp1;
                    unsigned bh0 = su[Vh_ + kg0 * 72 + n0];
                    unsigned bh1 = su[Vh_ + kg1 * 72 + n0];
                    unsigned bl0 = su[Vl_ + kg0 * 72 + n0];
                    unsigned bl1 = su[Vl_ + kg1 * 72 + n0];
                    mma16(rh, ah, bh0, bh1);
                    mma16(re, ah, bl0, bl1);
                    mma16(re, al, bh0, bh1);
                }
                float r0 = rh[0] + re[0], r1 = rh[1] + re[1];
                float r2 = rh[2] + re[2], r3 = rh[3] + re[3];
                rr[grp * 4 + 0] = r0; rr[grp * 4 + 1] = r1;
                rr[grp * 4 + 2] = r2; rr[grp * 4 + 3] = r3;
                float t0 = r0 + sm[H32_ + dc0 * 68 + ra0];
                float t1 = r1 + sm[H32_ + dc1 * 68 + ra0];
                float t2 = r2 + sm[H32_ + dc0 * 68 + ra1];
                float t3 = r3 + sm[H32_ + dc1 * 68 + ra1];
                unsigned short h0, l0, h1, l1;
                bsplit(t0, h0, l0); bsplit(t1, h1, l1);
                su[Th_ + ra0 * 36 + kpT] = pk16(h0, h1);
                su[Tl_ + ra0 * 36 + kpT] = pk16(l0, l1);
                bsplit(t2, h0, l0); bsplit(t3, h1, l1);
                su[Th_ + ra1 * 36 + kpT] = pk16(h0, h1);
                su[Tl_ + ra1 * 36 + kpT] = pk16(l0, l1);
            }
        }
        __syncthreads();

        // ---- E: G1 = gelu(Wg1 T + bg1) ----
        {
            int n0 = nt * 8 + qg;
            int dc0 = nt * 8 + 2 * t4, dc1 = dc0 + 1;
            float b0 = sm[BG1_ + dc0], b1 = sm[BG1_ + dc1];
            int kpT = nt * 4 + t4;
            float gh[2][4] = {}, ge[2][4] = {};
#pragma unroll
            for (int kt = 0; kt < 4; ++kt) {
                int kp0 = kt * 8 + t4, kp1 = kp0 + 4;
                unsigned bh0 = su[WG1h_ + kp0 * 72 + n0];
                unsigned bh1 = su[WG1h_ + kp1 * 72 + n0];
                unsigned bl0 = su[WG1l_ + kp0 * 72 + n0];
                unsigned bl1 = su[WG1l_ + kp1 * 72 + n0];
#pragma unroll
                for (int t = 0; t < 2; ++t) {
                    int ra0 = t * 32 + mt0 * 16 + qg, ra1 = ra0 + 8;
                    unsigned ah[4], al[4];
                    ah[0] = su[Th_ + ra0 * 36 + kp0];
                    ah[1] = su[Th_ + ra1 * 36 + kp0];
                    ah[2] = su[Th_ + ra0 * 36 + kp1];
                    ah[3] = su[Th_ + ra1 * 36 + kp1];
                    al[0] = su[Tl_ + ra0 * 36 + kp0];
                    al[1] = su[Tl_ + ra1 * 36 + kp0];
                    al[2] = su[Tl_ + ra0 * 36 + kp1];
                    al[3] = su[Tl_ + ra1 * 36 + kp1];
                    mma16(gh[t], ah, bh0, bh1);
                    mma16(ge[t], ah, bl0, bl1);
                    mma16(ge[t], al, bh0, bh1);
                }
            }
#pragma unroll
            for (int t = 0; t < 2; ++t) {
                int ra0 = t * 32 + mt0 * 16 + qg, ra1 = ra0 + 8;
                float g0 = gelu_exact(gh[t][0] + ge[t][0] + b0);
                float g1 = gelu_exact(gh[t][1] + ge[t][1] + b1);
                float g2 = gelu_exact(gh[t][2] + ge[t][2] + b0);
                float g3 = gelu_exact(gh[t][3] + ge[t][3] + b1);
                unsigned short h0, l0, h1, l1;
                bsplit(g0, h0, l0); bsplit(g1, h1, l1);
                su[G1h_ + ra0 * 36 + kpT] = pk16(h0, h1);
                su[G1l_ + ra0 * 36 + kpT] = pk16(l0, l1);
                bsplit(g2, h0, l0); bsplit(g3, h1, l1);
                su[G1h_ + ra1 * 36 + kpT] = pk16(h0, h1);
                su[G1l_ + ra1 * 36 + kpT] = pk16(l0, l1);
            }
        }
        __syncthreads();

        // ---- F: out = Wg2 G1 + bg2 + res ; maxpool ----
        {
            int n0 = nt * 8 + qg;
            int dc0 = nt * 8 + 2 * t4, dc1 = dc0 + 1;
            float b0 = sm[BG2_ + dc0], b1 = sm[BG2_ + dc1];
            float fh[2][4] = {}, fe[2][4] = {};
#pragma unroll
            for (int kt = 0; kt < 4; ++kt) {
                int kp0 = kt * 8 + t4, kp1 = kp0 + 4;
                unsigned bh0 = su[WG2h_ + kp0 * 72 + n0];
                unsigned bh1 = su[WG2h_ + kp1 * 72 + n0];
                unsigned bl0 = su[WG2l_ + kp0 * 72 + n0];
                unsigned bl1 = su[WG2l_ + kp1 * 72 + n0];
#pragma unroll
                for (int t = 0; t < 2; ++t) {
                    int ra0 = t * 32 + mt0 * 16 + qg, ra1 = ra0 + 8;
                    unsigned ah[4], al[4];
                    ah[0] = su[G1h_ + ra0 * 36 + kp0];
                    ah[1] = su[G1h_ + ra1 * 36 + kp0];
                    ah[2] = su[G1h_ + ra0 * 36 + kp1];
                    ah[3] = su[G1h_ + ra1 * 36 + kp1];
                    al[0] = su[G1l_ + ra0 * 36 + kp0];
                    al[1] = su[G1l_ + ra1 * 36 + kp0];
                    al[2] = su[G1l_ + ra0 * 36 + kp1];
                    al[3] = su[G1l_ + ra1 * 36 + kp1];
                    mma16(fh[t], ah, bh0, bh1);
                    mma16(fe[t], ah, bl0, bl1);
                    mma16(fe[t], al, bh0, bh1);
                }
            }
#pragma unroll
            for (int t = 0; t < 2; ++t) {
                float v0 = fh[t][0] + fe[t][0] + b0 + rr[t * 4 + 0];
                float v1 = fh[t][1] + fe[t][1] + b1 + rr[t * 4 + 1];
                float v2 = fh[t][2] + fe[t][2] + b0 + rr[t * 4 + 2];
                float v3 = fh[t][3] + fe[t][3] + b1 + rr[t * 4 + 3];
                float m0 = fmaxf(v0, v2), m1 = fmaxf(v1, v3);
#pragma unroll
                for (int off = 4; off < 32; off <<= 1) {
                    m0 = fmaxf(m0, __shfl_xor_sync(FULLMASK, m0, off));
                    m1 = fmaxf(m1, __shfl_xor_sync(FULLMASK, m1, off));
                }
                if (lane < 4) {
                    sm[MP_ + t * 128 + mt0 * 64 + nt * 8 + 2 * t4]     = m0;
                    sm[MP_ + t * 128 + mt0 * 64 + nt * 8 + 2 * t4 + 1] = m1;
                }
            }
        }
        __syncthreads();
        if (tid < 128) {
            int grp = tid >> 6, d = tid & 63;
            out[(size_t)(2 * p + grp) * 67 + 3 + d] =
                fmaxf(sm[MP_ + grp * 128 + d], sm[MP_ + grp * 128 + 64 + d]);
        }
        __syncthreads();
    }
}

// ============================ launch ======================================
extern "C" void kernel_launch(void* const* d_in, const int* in_sizes, int n_in,
                              void* d_out, int out_size) {
    (void)in_sizes; (void)n_in; (void)out_size;
    const float* x        = (const float*)d_in[0];
    const float* w_alpha  = (const float*)d_in[1];
    const float* b_alpha  = (const float*)d_in[2];
    const float* bn_gamma = (const float*)d_in[3];
    const float* bn_beta  = (const float*)d_in[4];
    const float* bn_mean  = (const float*)d_in[5];
    const float* bn_var   = (const float*)d_in[6];
    const float* w_q      = (const float*)d_in[7];
    const float* b_q      = (const float*)d_in[8];
    const float* w_k      = (const float*)d_in[9];
    const float* b_k      = (const float*)d_in[10];
    const float* w_v      = (const float*)d_in[11];
    const float* b_v      = (const float*)d_in[12];
    const float* w_g1     = (const float*)d_in[13];
    const float* b_g1     = (const float*)d_in[14];
    const float* w_g2     = (const float*)d_in[15];
    const float* b_g2     = (const float*)d_in[16];
    float* out = (float*)d_out;

    cudaFuncSetAttribute(fps_kernel,
                         cudaFuncAttributeMaxDynamicSharedMemorySize, 49664);
    cudaFuncSetAttribute(knn_kernel,
                         cudaFuncAttributeMaxDynamicSharedMemorySize, 65536);
    cudaFuncSetAttribute(group_kernel,
                         cudaFuncAttributeMaxDynamicSharedMemorySize, SMTOT * 4);

    fps_kernel<<<B_, 512, 49664>>>(x, out);
    knn_kernel<<<B_ * 4, 1024, 65536>>>(x);
    group_kernel<<<148, 512, SMTOT * 4>>>(w_alpha, b_alpha, bn_gamma, bn_beta,
                                          bn_mean, bn_var, w_q, b_q, w_k, b_k,
                                          w_v, b_v, w_g1, b_g1, w_g2, b_g2, out);
}